// round 1
// baseline (speedup 1.0000x reference)
#include <cuda_runtime.h>
#include <cuda_bf16.h>
#include <cstdint>

// Problem constants (match reference)
#define NN    8192        // nodes
#define EE    262144      // edges
#define FIN   512
#define HH    256
#define LL    64
#define P2    128         // 2*L (W2 and W3 concatenated)

// ---------------- device scratch (no allocation allowed) ----------------
__device__ float g_X1[NN * HH];        // features @ W1^T          [N,256]
__device__ float g_hidden[NN * HH];    // relu(agg1 + b1)          [N,256]
__device__ float g_P[NN * P2];         // hidden @ [W2;W3]^T       [N,128]
__device__ int   g_cnt[NN];
__device__ int   g_rowstart[NN + 1];
__device__ int   g_cursor[NN];
__device__ int   g_csr[EE];            // src indices grouped by dst

// ---------------- CSR build ----------------
__global__ void zero_counts_kernel() {
    int i = blockIdx.x * blockDim.x + threadIdx.x;
    if (i < NN) g_cnt[i] = 0;
}

__global__ void count_kernel(const int* __restrict__ dst) {
    int e = blockIdx.x * blockDim.x + threadIdx.x;
    if (e < EE) atomicAdd(&g_cnt[dst[e]], 1);
}

// single-block exclusive scan over 8192 counts (256 threads x 32 each)
__global__ void scan_kernel() {
    __shared__ int ssum[256];
    int t = threadIdx.x;
    int base = t * 32;
    int vals[32];
    int s = 0;
#pragma unroll
    for (int j = 0; j < 32; j++) { vals[j] = g_cnt[base + j]; s += vals[j]; }
    ssum[t] = s;
    __syncthreads();
#pragma unroll
    for (int off = 1; off < 256; off <<= 1) {
        int v = (t >= off) ? ssum[t - off] : 0;
        __syncthreads();
        ssum[t] += v;
        __syncthreads();
    }
    int run = ssum[t] - s;  // exclusive prefix of this thread's chunk
#pragma unroll
    for (int j = 0; j < 32; j++) {
        g_rowstart[base + j] = run;
        g_cursor[base + j]   = run;
        run += vals[j];
    }
    if (t == 255) g_rowstart[NN] = run;
}

__global__ void fill_kernel(const int* __restrict__ src, const int* __restrict__ dst) {
    int e = blockIdx.x * blockDim.x + threadIdx.x;
    if (e < EE) {
        int d = dst[e];
        int pos = atomicAdd(&g_cursor[d], 1);
        g_csr[pos] = src[e];
    }
}

// ---------------- generic fp32 GEMM: C[M,Nd] = A[M,K] @ Brow[Nd,K]^T ----------------
// B rows come from B1 (rows < split) or B2 (rows >= split), both [*,K] row-major.
// BM=128, BN=64, BK=32, 256 threads, 8x4 per thread.
__global__ __launch_bounds__(256) void gemm_tn_kernel(
    const float* __restrict__ A,
    const float* __restrict__ B1,
    const float* __restrict__ B2,
    int split,
    float* __restrict__ C,
    int M, int Nd, int K)
{
    const int BM = 128, BN = 64, BK = 32;
    __shared__ float As[BK][BM + 1];
    __shared__ float Bs[BK][BN + 1];

    int tid = threadIdx.x;
    int tx = tid & 15;       // 16 col groups of 4
    int ty = tid >> 4;       // 16 row groups of 8
    int m0 = blockIdx.y * BM;
    int n0 = blockIdx.x * BN;

    float acc[8][4];
#pragma unroll
    for (int r = 0; r < 8; r++)
#pragma unroll
        for (int c = 0; c < 4; c++) acc[r][c] = 0.f;

    for (int kt = 0; kt < K; kt += BK) {
        // load A tile (128 x 32) : 1024 float4 / 256 threads = 4 each
#pragma unroll
        for (int it = 0; it < 4; it++) {
            int l = it * 256 + tid;
            int row = l >> 3;          // 8 float4 per row
            int kq  = l & 7;
            float4 v = *(const float4*)(A + (size_t)(m0 + row) * K + kt + kq * 4);
            As[kq * 4 + 0][row] = v.x;
            As[kq * 4 + 1][row] = v.y;
            As[kq * 4 + 2][row] = v.z;
            As[kq * 4 + 3][row] = v.w;
        }
        // load B tile (64 x 32) : 512 float4 / 256 threads = 2 each
#pragma unroll
        for (int it = 0; it < 2; it++) {
            int l = it * 256 + tid;
            int col = l >> 3;
            int kq  = l & 7;
            int grow = n0 + col;
            const float* bp = (grow < split) ? (B1 + (size_t)grow * K)
                                             : (B2 + (size_t)(grow - split) * K);
            float4 v = *(const float4*)(bp + kt + kq * 4);
            Bs[kq * 4 + 0][col] = v.x;
            Bs[kq * 4 + 1][col] = v.y;
            Bs[kq * 4 + 2][col] = v.z;
            Bs[kq * 4 + 3][col] = v.w;
        }
        __syncthreads();
#pragma unroll
        for (int kk = 0; kk < BK; kk++) {
            float a[8], b[4];
#pragma unroll
            for (int r = 0; r < 8; r++) a[r] = As[kk][ty * 8 + r];
#pragma unroll
            for (int c = 0; c < 4; c++) b[c] = Bs[kk][tx * 4 + c];
#pragma unroll
            for (int r = 0; r < 8; r++)
#pragma unroll
                for (int c = 0; c < 4; c++) acc[r][c] += a[r] * b[c];
        }
        __syncthreads();
    }

#pragma unroll
    for (int r = 0; r < 8; r++) {
        float* cp = C + (size_t)(m0 + ty * 8 + r) * Nd + n0 + tx * 4;
        float4 v = make_float4(acc[r][0], acc[r][1], acc[r][2], acc[r][3]);
        *(float4*)cp = v;
    }
}

// ---------------- aggregation 1: hidden = relu(segsum(X1[src]->dst) + b1) ----------------
// 4 nodes per block, 64 threads (float4 columns) per node
__global__ __launch_bounds__(256) void agg1_relu_kernel(const float* __restrict__ b1) {
    int node = blockIdx.x * 4 + (threadIdx.x >> 6);
    int lane = threadIdx.x & 63;
    int s = g_rowstart[node];
    int e = g_rowstart[node + 1];
    float4 acc = make_float4(0.f, 0.f, 0.f, 0.f);
    int j = s;
    for (; j + 4 <= e; j += 4) {
        int i0 = g_csr[j + 0], i1 = g_csr[j + 1], i2 = g_csr[j + 2], i3 = g_csr[j + 3];
        float4 v0 = *(const float4*)(g_X1 + (size_t)i0 * HH + lane * 4);
        float4 v1 = *(const float4*)(g_X1 + (size_t)i1 * HH + lane * 4);
        float4 v2 = *(const float4*)(g_X1 + (size_t)i2 * HH + lane * 4);
        float4 v3 = *(const float4*)(g_X1 + (size_t)i3 * HH + lane * 4);
        acc.x += v0.x + v1.x + v2.x + v3.x;
        acc.y += v0.y + v1.y + v2.y + v3.y;
        acc.z += v0.z + v1.z + v2.z + v3.z;
        acc.w += v0.w + v1.w + v2.w + v3.w;
    }
    for (; j < e; j++) {
        int i0 = g_csr[j];
        float4 v0 = *(const float4*)(g_X1 + (size_t)i0 * HH + lane * 4);
        acc.x += v0.x; acc.y += v0.y; acc.z += v0.z; acc.w += v0.w;
    }
    float4 bb = ((const float4*)b1)[lane];
    acc.x = fmaxf(acc.x + bb.x, 0.f);
    acc.y = fmaxf(acc.y + bb.y, 0.f);
    acc.z = fmaxf(acc.z + bb.z, 0.f);
    acc.w = fmaxf(acc.w + bb.w, 0.f);
    *(float4*)(g_hidden + (size_t)node * HH + lane * 4) = acc;
}

// ---------------- aggregation 2: mu/logvar = segsum(P[src]->dst) + b2/b3 ----------------
// 8 nodes per block, 32 threads (float4 columns over 128) per node
__global__ __launch_bounds__(256) void agg2_bias_kernel(
    const float* __restrict__ b2, const float* __restrict__ b3,
    float* __restrict__ out_mu, float* __restrict__ out_lv)
{
    int node = blockIdx.x * 8 + (threadIdx.x >> 5);
    int lane = threadIdx.x & 31;
    int s = g_rowstart[node];
    int e = g_rowstart[node + 1];
    float4 acc = make_float4(0.f, 0.f, 0.f, 0.f);
    int j = s;
    for (; j + 4 <= e; j += 4) {
        int i0 = g_csr[j + 0], i1 = g_csr[j + 1], i2 = g_csr[j + 2], i3 = g_csr[j + 3];
        float4 v0 = *(const float4*)(g_P + (size_t)i0 * P2 + lane * 4);
        float4 v1 = *(const float4*)(g_P + (size_t)i1 * P2 + lane * 4);
        float4 v2 = *(const float4*)(g_P + (size_t)i2 * P2 + lane * 4);
        float4 v3 = *(const float4*)(g_P + (size_t)i3 * P2 + lane * 4);
        acc.x += v0.x + v1.x + v2.x + v3.x;
        acc.y += v0.y + v1.y + v2.y + v3.y;
        acc.z += v0.z + v1.z + v2.z + v3.z;
        acc.w += v0.w + v1.w + v2.w + v3.w;
    }
    for (; j < e; j++) {
        int i0 = g_csr[j];
        float4 v0 = *(const float4*)(g_P + (size_t)i0 * P2 + lane * 4);
        acc.x += v0.x; acc.y += v0.y; acc.z += v0.z; acc.w += v0.w;
    }
    if (lane < 16) {
        float4 bb = ((const float4*)b2)[lane];
        acc.x += bb.x; acc.y += bb.y; acc.z += bb.z; acc.w += bb.w;
        *(float4*)(out_mu + (size_t)node * LL + lane * 4) = acc;
    } else {
        float4 bb = ((const float4*)b3)[lane - 16];
        acc.x += bb.x; acc.y += bb.y; acc.z += bb.z; acc.w += bb.w;
        *(float4*)(out_lv + (size_t)node * LL + (lane - 16) * 4) = acc;
    }
}

// ---------------- adj = sigmoid(Z @ Z^T), Z = mu [8192, 64] ----------------
__device__ __forceinline__ float sigmoidf_fast(float x) {
    return __fdividef(1.0f, 1.0f + __expf(-x));
}

// BM=BN=128, BK=32 (2 outer iters), 256 threads, 8x8 per thread
__global__ __launch_bounds__(256) void gemm3_adj_kernel(
    const float* __restrict__ Z, float* __restrict__ adj)
{
    __shared__ float As[32][129];
    __shared__ float Bs[32][129];
    int tid = threadIdx.x;
    int tx = tid & 15;
    int ty = tid >> 4;
    int m0 = blockIdx.y * 128;
    int n0 = blockIdx.x * 128;

    float acc[8][8];
#pragma unroll
    for (int r = 0; r < 8; r++)
#pragma unroll
        for (int c = 0; c < 8; c++) acc[r][c] = 0.f;

#pragma unroll
    for (int kt = 0; kt < 64; kt += 32) {
        // A tile: 128 rows x 32 k = 1024 float4 / 256 = 4 each
#pragma unroll
        for (int it = 0; it < 4; it++) {
            int l = it * 256 + tid;
            int row = l >> 3;
            int kq  = l & 7;
            float4 v = *(const float4*)(Z + (size_t)(m0 + row) * LL + kt + kq * 4);
            As[kq * 4 + 0][row] = v.x;
            As[kq * 4 + 1][row] = v.y;
            As[kq * 4 + 2][row] = v.z;
            As[kq * 4 + 3][row] = v.w;
        }
#pragma unroll
        for (int it = 0; it < 4; it++) {
            int l = it * 256 + tid;
            int row = l >> 3;
            int kq  = l & 7;
            float4 v = *(const float4*)(Z + (size_t)(n0 + row) * LL + kt + kq * 4);
            Bs[kq * 4 + 0][row] = v.x;
            Bs[kq * 4 + 1][row] = v.y;
            Bs[kq * 4 + 2][row] = v.z;
            Bs[kq * 4 + 3][row] = v.w;
        }
        __syncthreads();
#pragma unroll
        for (int kk = 0; kk < 32; kk++) {
            float a[8], b[8];
#pragma unroll
            for (int r = 0; r < 8; r++) a[r] = As[kk][ty * 8 + r];
#pragma unroll
            for (int c = 0; c < 8; c++) b[c] = Bs[kk][tx * 8 + c];
#pragma unroll
            for (int r = 0; r < 8; r++)
#pragma unroll
                for (int c = 0; c < 8; c++) acc[r][c] += a[r] * b[c];
        }
        __syncthreads();
    }

#pragma unroll
    for (int r = 0; r < 8; r++) {
        float* op = adj + (size_t)(m0 + ty * 8 + r) * NN + n0 + tx * 8;
        float4 v0, v1;
        v0.x = sigmoidf_fast(acc[r][0]);
        v0.y = sigmoidf_fast(acc[r][1]);
        v0.z = sigmoidf_fast(acc[r][2]);
        v0.w = sigmoidf_fast(acc[r][3]);
        v1.x = sigmoidf_fast(acc[r][4]);
        v1.y = sigmoidf_fast(acc[r][5]);
        v1.z = sigmoidf_fast(acc[r][6]);
        v1.w = sigmoidf_fast(acc[r][7]);
        *(float4*)(op)     = v0;
        *(float4*)(op + 4) = v1;
    }
}

// ---------------- launch ----------------
extern "C" void kernel_launch(void* const* d_in, const int* in_sizes, int n_in,
                              void* d_out, int out_size)
{
    const float* features = (const float*)d_in[0];
    const int*   src      = (const int*)  d_in[1];
    const int*   dst      = (const int*)  d_in[2];
    const float* W1       = (const float*)d_in[3];
    const float* b1       = (const float*)d_in[4];
    const float* W2       = (const float*)d_in[5];
    const float* b2       = (const float*)d_in[6];
    const float* W3       = (const float*)d_in[7];
    const float* b3       = (const float*)d_in[8];

    float* adj = (float*)d_out;
    float* mu  = adj + (size_t)NN * NN;
    float* lv  = mu  + (size_t)NN * LL;

    float *x1p, *hidp, *pp;
    cudaGetSymbolAddress((void**)&x1p,  g_X1);
    cudaGetSymbolAddress((void**)&hidp, g_hidden);
    cudaGetSymbolAddress((void**)&pp,   g_P);

    // CSR build
    zero_counts_kernel<<<NN / 256, 256>>>();
    count_kernel<<<EE / 256, 256>>>(dst);
    scan_kernel<<<1, 256>>>();
    fill_kernel<<<EE / 256, 256>>>(src, dst);

    // X1 = features @ W1^T   [8192,256]
    gemm_tn_kernel<<<dim3(HH / 64, NN / 128), 256>>>(
        features, W1, W1, HH, x1p, NN, HH, FIN);

    // hidden = relu(segsum(X1) + b1)
    agg1_relu_kernel<<<NN / 4, 256>>>(b1);

    // P = hidden @ [W2;W3]^T   [8192,128]
    gemm_tn_kernel<<<dim3(P2 / 64, NN / 128), 256>>>(
        hidp, W2, W3, LL, pp, NN, P2, HH);

    // mu / logvar = segsum(P) + b2/b3   (written straight into d_out)
    agg2_bias_kernel<<<NN / 8, 256>>>(b2, b3, mu, lv);

    // adj = sigmoid(mu @ mu^T)
    gemm3_adj_kernel<<<dim3(NN / 128, NN / 128), 256>>>(mu, adj);
}

// round 3
// speedup vs baseline: 1.4441x; 1.4441x over previous
#include <cuda_runtime.h>
#include <cuda_bf16.h>
#include <cstdint>

// Problem constants (match reference)
#define NN    8192        // nodes
#define EE    262144      // edges
#define FIN   512
#define HH    256
#define LL    64
#define P2    128         // 2*L (W2 and W3 concatenated)

// ---------------- device scratch (no allocation allowed) ----------------
__device__ float g_X1[NN * HH];        // features @ W1^T          [N,256]
__device__ float g_hidden[NN * HH];    // relu(agg1 + b1)          [N,256]
__device__ float g_P[NN * P2];         // hidden @ [W2;W3]^T       [N,128]
__device__ int   g_cnt[NN];
__device__ int   g_rowstart[NN + 1];
__device__ int   g_cursor[NN];
__device__ int   g_csr[EE];            // src indices grouped by dst

// split-bf16 concatenated operands for the adj GEMM (K = 3*64 = 192)
// A_cat[m] = [hi, hi, lo],  B_cat[n] = [hi, lo, hi]
__device__ __align__(256) __nv_bfloat16 g_Acat[NN * 192];
__device__ __align__(256) __nv_bfloat16 g_Bcat[NN * 192];

// ---------------- CSR build ----------------
__global__ void zero_counts_kernel() {
    int i = blockIdx.x * blockDim.x + threadIdx.x;
    if (i < NN) g_cnt[i] = 0;
}

__global__ void count_kernel(const int* __restrict__ dst) {
    int e = blockIdx.x * blockDim.x + threadIdx.x;
    if (e < EE) atomicAdd(&g_cnt[dst[e]], 1);
}

__global__ void scan_kernel() {
    __shared__ int ssum[256];
    int t = threadIdx.x;
    int base = t * 32;
    int vals[32];
    int s = 0;
#pragma unroll
    for (int j = 0; j < 32; j++) { vals[j] = g_cnt[base + j]; s += vals[j]; }
    ssum[t] = s;
    __syncthreads();
#pragma unroll
    for (int off = 1; off < 256; off <<= 1) {
        int v = (t >= off) ? ssum[t - off] : 0;
        __syncthreads();
        ssum[t] += v;
        __syncthreads();
    }
    int run = ssum[t] - s;
#pragma unroll
    for (int j = 0; j < 32; j++) {
        g_rowstart[base + j] = run;
        g_cursor[base + j]   = run;
        run += vals[j];
    }
    if (t == 255) g_rowstart[NN] = run;
}

__global__ void fill_kernel(const int* __restrict__ src, const int* __restrict__ dst) {
    int e = blockIdx.x * blockDim.x + threadIdx.x;
    if (e < EE) {
        int d = dst[e];
        int pos = atomicAdd(&g_cursor[d], 1);
        g_csr[pos] = src[e];
    }
}

// ---------------- generic fp32 GEMM: C[M,Nd] = A[M,K] @ Brow[Nd,K]^T ----------------
__global__ __launch_bounds__(256) void gemm_tn_kernel(
    const float* __restrict__ A,
    const float* __restrict__ B1,
    const float* __restrict__ B2,
    int split,
    float* __restrict__ C,
    int M, int Nd, int K)
{
    const int BM = 128, BN = 64, BK = 32;
    __shared__ float As[BK][BM + 1];
    __shared__ float Bs[BK][BN + 1];

    int tid = threadIdx.x;
    int tx = tid & 15;
    int ty = tid >> 4;
    int m0 = blockIdx.y * BM;
    int n0 = blockIdx.x * BN;

    float acc[8][4];
#pragma unroll
    for (int r = 0; r < 8; r++)
#pragma unroll
        for (int c = 0; c < 4; c++) acc[r][c] = 0.f;

    for (int kt = 0; kt < K; kt += BK) {
#pragma unroll
        for (int it = 0; it < 4; it++) {
            int l = it * 256 + tid;
            int row = l >> 3;
            int kq  = l & 7;
            float4 v = *(const float4*)(A + (size_t)(m0 + row) * K + kt + kq * 4);
            As[kq * 4 + 0][row] = v.x;
            As[kq * 4 + 1][row] = v.y;
            As[kq * 4 + 2][row] = v.z;
            As[kq * 4 + 3][row] = v.w;
        }
#pragma unroll
        for (int it = 0; it < 2; it++) {
            int l = it * 256 + tid;
            int col = l >> 3;
            int kq  = l & 7;
            int grow = n0 + col;
            const float* bp = (grow < split) ? (B1 + (size_t)grow * K)
                                             : (B2 + (size_t)(grow - split) * K);
            float4 v = *(const float4*)(bp + kt + kq * 4);
            Bs[kq * 4 + 0][col] = v.x;
            Bs[kq * 4 + 1][col] = v.y;
            Bs[kq * 4 + 2][col] = v.z;
            Bs[kq * 4 + 3][col] = v.w;
        }
        __syncthreads();
#pragma unroll
        for (int kk = 0; kk < BK; kk++) {
            float a[8], b[4];
#pragma unroll
            for (int r = 0; r < 8; r++) a[r] = As[kk][ty * 8 + r];
#pragma unroll
            for (int c = 0; c < 4; c++) b[c] = Bs[kk][tx * 4 + c];
#pragma unroll
            for (int r = 0; r < 8; r++)
#pragma unroll
                for (int c = 0; c < 4; c++) acc[r][c] += a[r] * b[c];
        }
        __syncthreads();
    }

#pragma unroll
    for (int r = 0; r < 8; r++) {
        float* cp = C + (size_t)(m0 + ty * 8 + r) * Nd + n0 + tx * 4;
        float4 v = make_float4(acc[r][0], acc[r][1], acc[r][2], acc[r][3]);
        *(float4*)cp = v;
    }
}

// ---------------- aggregation 1 ----------------
__global__ __launch_bounds__(256) void agg1_relu_kernel(const float* __restrict__ b1) {
    int node = blockIdx.x * 4 + (threadIdx.x >> 6);
    int lane = threadIdx.x & 63;
    int s = g_rowstart[node];
    int e = g_rowstart[node + 1];
    float4 acc = make_float4(0.f, 0.f, 0.f, 0.f);
    int j = s;
    for (; j + 4 <= e; j += 4) {
        int i0 = g_csr[j + 0], i1 = g_csr[j + 1], i2 = g_csr[j + 2], i3 = g_csr[j + 3];
        float4 v0 = *(const float4*)(g_X1 + (size_t)i0 * HH + lane * 4);
        float4 v1 = *(const float4*)(g_X1 + (size_t)i1 * HH + lane * 4);
        float4 v2 = *(const float4*)(g_X1 + (size_t)i2 * HH + lane * 4);
        float4 v3 = *(const float4*)(g_X1 + (size_t)i3 * HH + lane * 4);
        acc.x += v0.x + v1.x + v2.x + v3.x;
        acc.y += v0.y + v1.y + v2.y + v3.y;
        acc.z += v0.z + v1.z + v2.z + v3.z;
        acc.w += v0.w + v1.w + v2.w + v3.w;
    }
    for (; j < e; j++) {
        int i0 = g_csr[j];
        float4 v0 = *(const float4*)(g_X1 + (size_t)i0 * HH + lane * 4);
        acc.x += v0.x; acc.y += v0.y; acc.z += v0.z; acc.w += v0.w;
    }
    float4 bb = ((const float4*)b1)[lane];
    acc.x = fmaxf(acc.x + bb.x, 0.f);
    acc.y = fmaxf(acc.y + bb.y, 0.f);
    acc.z = fmaxf(acc.z + bb.z, 0.f);
    acc.w = fmaxf(acc.w + bb.w, 0.f);
    *(float4*)(g_hidden + (size_t)node * HH + lane * 4) = acc;
}

// ---------------- aggregation 2 ----------------
__global__ __launch_bounds__(256) void agg2_bias_kernel(
    const float* __restrict__ b2, const float* __restrict__ b3,
    float* __restrict__ out_mu, float* __restrict__ out_lv)
{
    int node = blockIdx.x * 8 + (threadIdx.x >> 5);
    int lane = threadIdx.x & 31;
    int s = g_rowstart[node];
    int e = g_rowstart[node + 1];
    float4 acc = make_float4(0.f, 0.f, 0.f, 0.f);
    int j = s;
    for (; j + 4 <= e; j += 4) {
        int i0 = g_csr[j + 0], i1 = g_csr[j + 1], i2 = g_csr[j + 2], i3 = g_csr[j + 3];
        float4 v0 = *(const float4*)(g_P + (size_t)i0 * P2 + lane * 4);
        float4 v1 = *(const float4*)(g_P + (size_t)i1 * P2 + lane * 4);
        float4 v2 = *(const float4*)(g_P + (size_t)i2 * P2 + lane * 4);
        float4 v3 = *(const float4*)(g_P + (size_t)i3 * P2 + lane * 4);
        acc.x += v0.x + v1.x + v2.x + v3.x;
        acc.y += v0.y + v1.y + v2.y + v3.y;
        acc.z += v0.z + v1.z + v2.z + v3.z;
        acc.w += v0.w + v1.w + v2.w + v3.w;
    }
    for (; j < e; j++) {
        int i0 = g_csr[j];
        float4 v0 = *(const float4*)(g_P + (size_t)i0 * P2 + lane * 4);
        acc.x += v0.x; acc.y += v0.y; acc.z += v0.z; acc.w += v0.w;
    }
    if (lane < 16) {
        float4 bb = ((const float4*)b2)[lane];
        acc.x += bb.x; acc.y += bb.y; acc.z += bb.z; acc.w += bb.w;
        *(float4*)(out_mu + (size_t)node * LL + lane * 4) = acc;
    } else {
        float4 bb = ((const float4*)b3)[lane - 16];
        acc.x += bb.x; acc.y += bb.y; acc.z += bb.z; acc.w += bb.w;
        *(float4*)(out_lv + (size_t)node * LL + (lane - 16) * 4) = acc;
    }
}

// ---------------- split z -> (hi, lo) concatenated bf16 operands ----------------
__global__ __launch_bounds__(256) void split_kernel(const float* __restrict__ z) {
    int i = blockIdx.x * blockDim.x + threadIdx.x;   // over NN*LL
    int m = i >> 6;
    int k = i & 63;
    float v = z[i];
    __nv_bfloat16 h = __float2bfloat16(v);
    __nv_bfloat16 l = __float2bfloat16(v - __bfloat162float(h));
    __nv_bfloat16* a = g_Acat + (size_t)m * 192;
    __nv_bfloat16* b = g_Bcat + (size_t)m * 192;
    a[k] = h;  a[64 + k] = h;  a[128 + k] = l;
    b[k] = h;  b[64 + k] = l;  b[128 + k] = h;
}

// ---------------- adj = sigmoid(Z @ Z^T) via mma.sync bf16 (split, K=192) ----------------
__device__ __forceinline__ float sigmoid_tanh(float x) {
    float t;
    asm("tanh.approx.f32 %0, %1;" : "=f"(t) : "f"(0.5f * x));
    return 0.5f * t + 0.5f;
}

__device__ __forceinline__ void mma_bf16(
    float* c, const uint32_t* a, const uint32_t* b)
{
    asm volatile(
        "mma.sync.aligned.m16n8k16.row.col.f32.bf16.bf16.f32 "
        "{%0,%1,%2,%3}, {%4,%5,%6,%7}, {%8,%9}, {%0,%1,%2,%3};"
        : "+f"(c[0]), "+f"(c[1]), "+f"(c[2]), "+f"(c[3])
        : "r"(a[0]), "r"(a[1]), "r"(a[2]), "r"(a[3]), "r"(b[0]), "r"(b[1]));
}

// SMEM: A tile [128][200] bf16 (rows padded 192->200 for bank-conflict-free frags),
//       B tile [128][200] bf16.  51200 B each.
#define G3_PAD   200
#define G3_ASZ   (128 * G3_PAD * 2)
#define G3_SMEM  (2 * G3_ASZ)

__global__ __launch_bounds__(256) void gemm3_mma_kernel(float* __restrict__ adj)
{
    extern __shared__ __align__(16) char smem[];
    __nv_bfloat16* sA = (__nv_bfloat16*)smem;
    __nv_bfloat16* sB = (__nv_bfloat16*)(smem + G3_ASZ);

    int tid  = threadIdx.x;
    int lane = tid & 31;
    int w    = tid >> 5;
    int m0 = blockIdx.y * 128;
    int n0 = blockIdx.x * 128;

    // cooperative tile load: 2 tiles x 128 rows x 24 uint4 (192 bf16/row)
    for (int i = tid; i < 2 * 128 * 24; i += 256) {
        int t   = (i >= 3072);
        int j   = t ? i - 3072 : i;
        int row = j / 24;
        int u   = j % 24;
        const __nv_bfloat16* g =
            (t ? g_Bcat + (size_t)(n0 + row) * 192
               : g_Acat + (size_t)(m0 + row) * 192) + u * 8;
        __nv_bfloat16* d = (t ? sB : sA) + row * G3_PAD + u * 8;
        *(uint4*)d = *(const uint4*)g;
    }
    __syncthreads();

    // warp tiling: 2x4 warps, each 64 (m) x 32 (n)
    int wm = (w >> 2) * 64;
    int wn = (w & 3) * 32;
    int grp = lane >> 2;       // 0..7
    int qid = lane & 3;        // 0..3

    float acc[4][4][4];
#pragma unroll
    for (int mt = 0; mt < 4; mt++)
#pragma unroll
        for (int nt = 0; nt < 4; nt++)
#pragma unroll
            for (int r = 0; r < 4; r++) acc[mt][nt][r] = 0.f;

#pragma unroll
    for (int ks = 0; ks < 12; ks++) {
        int k0 = ks * 16 + qid * 2;
        uint32_t a[4][4], b[4][2];
#pragma unroll
        for (int mt = 0; mt < 4; mt++) {
            const __nv_bfloat16* base = sA + (wm + mt * 16 + grp) * G3_PAD;
            a[mt][0] = *(const uint32_t*)(base + k0);
            a[mt][1] = *(const uint32_t*)(base + 8 * G3_PAD + k0);
            a[mt][2] = *(const uint32_t*)(base + k0 + 8);
            a[mt][3] = *(const uint32_t*)(base + 8 * G3_PAD + k0 + 8);
        }
#pragma unroll
        for (int nt = 0; nt < 4; nt++) {
            const __nv_bfloat16* base = sB + (wn + nt * 8 + grp) * G3_PAD;
            b[nt][0] = *(const uint32_t*)(base + k0);
            b[nt][1] = *(const uint32_t*)(base + k0 + 8);
        }
#pragma unroll
        for (int mt = 0; mt < 4; mt++)
#pragma unroll
            for (int nt = 0; nt < 4; nt++)
                mma_bf16(acc[mt][nt], a[mt], b[nt]);
    }

    // epilogue: sigmoid + direct stores (float2; 4-lane groups write 32B sectors)
#pragma unroll
    for (int mt = 0; mt < 4; mt++) {
        int row = m0 + wm + mt * 16 + grp;
#pragma unroll
        for (int nt = 0; nt < 4; nt++) {
            int col = n0 + wn + nt * 8 + qid * 2;
            float2 v0, v1;
            v0.x = sigmoid_tanh(acc[mt][nt][0]);
            v0.y = sigmoid_tanh(acc[mt][nt][1]);
            v1.x = sigmoid_tanh(acc[mt][nt][2]);
            v1.y = sigmoid_tanh(acc[mt][nt][3]);
            *(float2*)(adj + (size_t)row * NN + col)       = v0;
            *(float2*)(adj + (size_t)(row + 8) * NN + col) = v1;
        }
    }
}

// ---------------- launch ----------------
extern "C" void kernel_launch(void* const* d_in, const int* in_sizes, int n_in,
                              void* d_out, int out_size)
{
    const float* features = (const float*)d_in[0];
    const int*   src      = (const int*)  d_in[1];
    const int*   dst      = (const int*)  d_in[2];
    const float* W1       = (const float*)d_in[3];
    const float* b1       = (const float*)d_in[4];
    const float* W2       = (const float*)d_in[5];
    const float* b2       = (const float*)d_in[6];
    const float* W3       = (const float*)d_in[7];
    const float* b3       = (const float*)d_in[8];

    float* adj = (float*)d_out;
    float* mu  = adj + (size_t)NN * NN;
    float* lv  = mu  + (size_t)NN * LL;

    float *x1p, *hidp, *pp;
    cudaGetSymbolAddress((void**)&x1p,  g_X1);
    cudaGetSymbolAddress((void**)&hidp, g_hidden);
    cudaGetSymbolAddress((void**)&pp,   g_P);

    cudaFuncSetAttribute(gemm3_mma_kernel,
                         cudaFuncAttributeMaxDynamicSharedMemorySize, G3_SMEM);

    // CSR build
    zero_counts_kernel<<<NN / 256, 256>>>();
    count_kernel<<<EE / 256, 256>>>(dst);
    scan_kernel<<<1, 256>>>();
    fill_kernel<<<EE / 256, 256>>>(src, dst);

    // X1 = features @ W1^T   [8192,256]
    gemm_tn_kernel<<<dim3(HH / 64, NN / 128), 256>>>(
        features, W1, W1, HH, x1p, NN, HH, FIN);

    // hidden = relu(segsum(X1) + b1)
    agg1_relu_kernel<<<NN / 4, 256>>>(b1);

    // P = hidden @ [W2;W3]^T   [8192,128]
    gemm_tn_kernel<<<dim3(P2 / 64, NN / 128), 256>>>(
        hidp, W2, W3, LL, pp, NN, P2, HH);

    // mu / logvar = segsum(P) + b2/b3   (written straight into d_out)
    agg2_bias_kernel<<<NN / 8, 256>>>(b2, b3, mu, lv);

    // split z = mu into bf16 hi/lo concatenated operands
    split_kernel<<<(NN * LL) / 256, 256>>>(mu);

    // adj = sigmoid(Z @ Z^T) via mma.sync split-bf16, K=192
    gemm3_mma_kernel<<<dim3(NN / 128, NN / 128), 256, G3_SMEM>>>(adj);
}

// round 4
// speedup vs baseline: 1.5736x; 1.0897x over previous
#include <cuda_runtime.h>
#include <cuda_bf16.h>
#include <cstdint>

// Problem constants (match reference)
#define NN    8192        // nodes
#define EE    262144      // edges
#define FIN   512
#define HH    256
#define LL    64
#define P2    128         // 2*L (W2 and W3 concatenated)

// ---------------- device scratch (no allocation allowed) ----------------
__device__ float g_X1[NN * HH];        // features @ W1^T          [N,256]
__device__ float g_hidden[NN * HH];    // relu(agg1 + b1)          [N,256]
__device__ float g_P[NN * P2];         // hidden @ [W2;W3]^T       [N,128]
__device__ int   g_cnt[NN];
__device__ int   g_rowstart[NN + 1];
__device__ int   g_cursor[NN];
__device__ int   g_csr[EE];            // src indices grouped by dst

// split-bf16 operand buffers
__device__ __align__(256) __nv_bfloat16 g_fhi[NN * FIN];   // features hi
__device__ __align__(256) __nv_bfloat16 g_flo[NN * FIN];   // features lo
__device__ __align__(256) __nv_bfloat16 g_w1hi[HH * FIN];
__device__ __align__(256) __nv_bfloat16 g_w1lo[HH * FIN];
__device__ __align__(256) __nv_bfloat16 g_hhi[NN * HH];    // hidden hi
__device__ __align__(256) __nv_bfloat16 g_hlo[NN * HH];
__device__ __align__(256) __nv_bfloat16 g_wchi[P2 * HH];   // [W2;W3] hi
__device__ __align__(256) __nv_bfloat16 g_wclo[P2 * HH];

// split-bf16 concatenated operands for the adj GEMM (K = 3*64 = 192)
// A_cat[m] = [hi, hi, lo],  B_cat[n] = [hi, lo, hi]
__device__ __align__(256) __nv_bfloat16 g_Acat[NN * 192];
__device__ __align__(256) __nv_bfloat16 g_Bcat[NN * 192];

// ---------------- CSR build ----------------
__global__ void zero_counts_kernel() {
    int i = blockIdx.x * blockDim.x + threadIdx.x;
    if (i < NN) g_cnt[i] = 0;
}

__global__ void count_kernel(const int* __restrict__ dst) {
    int e = blockIdx.x * blockDim.x + threadIdx.x;
    if (e < EE) atomicAdd(&g_cnt[dst[e]], 1);
}

__global__ void scan_kernel() {
    __shared__ int ssum[256];
    int t = threadIdx.x;
    int base = t * 32;
    int vals[32];
    int s = 0;
#pragma unroll
    for (int j = 0; j < 32; j++) { vals[j] = g_cnt[base + j]; s += vals[j]; }
    ssum[t] = s;
    __syncthreads();
#pragma unroll
    for (int off = 1; off < 256; off <<= 1) {
        int v = (t >= off) ? ssum[t - off] : 0;
        __syncthreads();
        ssum[t] += v;
        __syncthreads();
    }
    int run = ssum[t] - s;
#pragma unroll
    for (int j = 0; j < 32; j++) {
        g_rowstart[base + j] = run;
        g_cursor[base + j]   = run;
        run += vals[j];
    }
    if (t == 255) g_rowstart[NN] = run;
}

__global__ void fill_kernel(const int* __restrict__ src, const int* __restrict__ dst) {
    int e = blockIdx.x * blockDim.x + threadIdx.x;
    if (e < EE) {
        int d = dst[e];
        int pos = atomicAdd(&g_cursor[d], 1);
        g_csr[pos] = src[e];
    }
}

// ---------------- fp32 -> bf16 hi/lo split (vectorized float4) ----------------
__global__ void conv_split_kernel(const float* __restrict__ in,
                                  __nv_bfloat16* __restrict__ hi,
                                  __nv_bfloat16* __restrict__ lo, int n4)
{
    int i = blockIdx.x * blockDim.x + threadIdx.x;
    if (i >= n4) return;
    float4 v = ((const float4*)in)[i];
    __nv_bfloat16 h0 = __float2bfloat16(v.x);
    __nv_bfloat16 h1 = __float2bfloat16(v.y);
    __nv_bfloat16 h2 = __float2bfloat16(v.z);
    __nv_bfloat16 h3 = __float2bfloat16(v.w);
    __nv_bfloat16 l0 = __float2bfloat16(v.x - __bfloat162float(h0));
    __nv_bfloat16 l1 = __float2bfloat16(v.y - __bfloat162float(h1));
    __nv_bfloat16 l2 = __float2bfloat16(v.z - __bfloat162float(h2));
    __nv_bfloat16 l3 = __float2bfloat16(v.w - __bfloat162float(h3));
    __nv_bfloat162* hp = (__nv_bfloat162*)(hi + i * 4);
    __nv_bfloat162* lp = (__nv_bfloat162*)(lo + i * 4);
    hp[0] = __nv_bfloat162(h0, h1);
    hp[1] = __nv_bfloat162(h2, h3);
    lp[0] = __nv_bfloat162(l0, l1);
    lp[1] = __nv_bfloat162(l2, l3);
}

// ---------------- bf16 mma primitive ----------------
__device__ __forceinline__ void mma_bf16(
    float* c, const uint32_t* a, const uint32_t* b)
{
    asm volatile(
        "mma.sync.aligned.m16n8k16.row.col.f32.bf16.bf16.f32 "
        "{%0,%1,%2,%3}, {%4,%5,%6,%7}, {%8,%9}, {%0,%1,%2,%3};"
        : "+f"(c[0]), "+f"(c[1]), "+f"(c[2]), "+f"(c[3])
        : "r"(a[0]), "r"(a[1]), "r"(a[2]), "r"(a[3]), "r"(b[0]), "r"(b[1]));
}

// ---------------- split-bf16 GEMM: C[M,Nd] = (Ahi+Alo)[M,K] @ (Bhi+Blo)[Nd,K]^T ----
// (drops lo*lo term). CTA 128x64, 8 warps of 32x32, BK=64, smem rows padded to 72.
#define G12_SMEM ((128 * 72 + 64 * 72) * 2 * 2)   // 55296 B

__global__ __launch_bounds__(256) void gemm12_kernel(
    const __nv_bfloat16* __restrict__ Ahi, const __nv_bfloat16* __restrict__ Alo,
    const __nv_bfloat16* __restrict__ Bhi, const __nv_bfloat16* __restrict__ Blo,
    float* __restrict__ C, int Nd, int K)
{
    extern __shared__ __align__(16) char sm12[];
    __nv_bfloat16* sAh = (__nv_bfloat16*)sm12;        // 128*72
    __nv_bfloat16* sAl = sAh + 128 * 72;
    __nv_bfloat16* sBh = sAl + 128 * 72;              // 64*72
    __nv_bfloat16* sBl = sBh + 64 * 72;

    int tid  = threadIdx.x;
    int lane = tid & 31;
    int w    = tid >> 5;
    int wm = (w >> 1) * 32;
    int wn = (w & 1) * 32;
    int grp = lane >> 2;
    int qid = lane & 3;
    int m0 = blockIdx.y * 128;
    int n0 = blockIdx.x * 64;

    float acc[2][4][4];
#pragma unroll
    for (int mt = 0; mt < 2; mt++)
#pragma unroll
        for (int nt = 0; nt < 4; nt++)
#pragma unroll
            for (int r = 0; r < 4; r++) acc[mt][nt][r] = 0.f;

    for (int kt = 0; kt < K; kt += 64) {
#pragma unroll
        for (int it = 0; it < 4; it++) {
            int i = it * 256 + tid;
            int row = i >> 3, u = i & 7;
            size_t go = (size_t)(m0 + row) * K + kt + u * 8;
            int so = row * 72 + u * 8;
            *(uint4*)(sAh + so) = *(const uint4*)(Ahi + go);
            *(uint4*)(sAl + so) = *(const uint4*)(Alo + go);
        }
#pragma unroll
        for (int it = 0; it < 2; it++) {
            int i = it * 256 + tid;
            int row = i >> 3, u = i & 7;
            size_t go = (size_t)(n0 + row) * K + kt + u * 8;
            int so = row * 72 + u * 8;
            *(uint4*)(sBh + so) = *(const uint4*)(Bhi + go);
            *(uint4*)(sBl + so) = *(const uint4*)(Blo + go);
        }
        __syncthreads();
#pragma unroll
        for (int ks = 0; ks < 4; ks++) {
            int k0 = ks * 16 + qid * 2;
            uint32_t ah[2][4], al[2][4], bh[4][2], bl[4][2];
#pragma unroll
            for (int mt = 0; mt < 2; mt++) {
                const __nv_bfloat16* p = sAh + (wm + mt * 16 + grp) * 72 + k0;
                ah[mt][0] = *(const uint32_t*)(p);
                ah[mt][1] = *(const uint32_t*)(p + 8 * 72);
                ah[mt][2] = *(const uint32_t*)(p + 8);
                ah[mt][3] = *(const uint32_t*)(p + 8 * 72 + 8);
                const __nv_bfloat16* q = sAl + (wm + mt * 16 + grp) * 72 + k0;
                al[mt][0] = *(const uint32_t*)(q);
                al[mt][1] = *(const uint32_t*)(q + 8 * 72);
                al[mt][2] = *(const uint32_t*)(q + 8);
                al[mt][3] = *(const uint32_t*)(q + 8 * 72 + 8);
            }
#pragma unroll
            for (int nt = 0; nt < 4; nt++) {
                const __nv_bfloat16* p = sBh + (wn + nt * 8 + grp) * 72 + k0;
                bh[nt][0] = *(const uint32_t*)(p);
                bh[nt][1] = *(const uint32_t*)(p + 8);
                const __nv_bfloat16* q = sBl + (wn + nt * 8 + grp) * 72 + k0;
                bl[nt][0] = *(const uint32_t*)(q);
                bl[nt][1] = *(const uint32_t*)(q + 8);
            }
#pragma unroll
            for (int mt = 0; mt < 2; mt++)
#pragma unroll
                for (int nt = 0; nt < 4; nt++) {
                    mma_bf16(acc[mt][nt], ah[mt], bh[nt]);
                    mma_bf16(acc[mt][nt], ah[mt], bl[nt]);
                    mma_bf16(acc[mt][nt], al[mt], bh[nt]);
                }
        }
        __syncthreads();
    }

#pragma unroll
    for (int mt = 0; mt < 2; mt++) {
        int row = m0 + wm + mt * 16 + grp;
#pragma unroll
        for (int nt = 0; nt < 4; nt++) {
            int col = n0 + wn + nt * 8 + qid * 2;
            float2 v0 = make_float2(acc[mt][nt][0], acc[mt][nt][1]);
            float2 v1 = make_float2(acc[mt][nt][2], acc[mt][nt][3]);
            *(float2*)(C + (size_t)row * Nd + col)       = v0;
            *(float2*)(C + (size_t)(row + 8) * Nd + col) = v1;
        }
    }
}

// ---------------- aggregation 1 ----------------
__global__ __launch_bounds__(256) void agg1_relu_kernel(const float* __restrict__ b1) {
    int node = blockIdx.x * 4 + (threadIdx.x >> 6);
    int lane = threadIdx.x & 63;
    int s = g_rowstart[node];
    int e = g_rowstart[node + 1];
    float4 acc = make_float4(0.f, 0.f, 0.f, 0.f);
    int j = s;
    for (; j + 4 <= e; j += 4) {
        int i0 = g_csr[j + 0], i1 = g_csr[j + 1], i2 = g_csr[j + 2], i3 = g_csr[j + 3];
        float4 v0 = *(const float4*)(g_X1 + (size_t)i0 * HH + lane * 4);
        float4 v1 = *(const float4*)(g_X1 + (size_t)i1 * HH + lane * 4);
        float4 v2 = *(const float4*)(g_X1 + (size_t)i2 * HH + lane * 4);
        float4 v3 = *(const float4*)(g_X1 + (size_t)i3 * HH + lane * 4);
        acc.x += v0.x + v1.x + v2.x + v3.x;
        acc.y += v0.y + v1.y + v2.y + v3.y;
        acc.z += v0.z + v1.z + v2.z + v3.z;
        acc.w += v0.w + v1.w + v2.w + v3.w;
    }
    for (; j < e; j++) {
        int i0 = g_csr[j];
        float4 v0 = *(const float4*)(g_X1 + (size_t)i0 * HH + lane * 4);
        acc.x += v0.x; acc.y += v0.y; acc.z += v0.z; acc.w += v0.w;
    }
    float4 bb = ((const float4*)b1)[lane];
    acc.x = fmaxf(acc.x + bb.x, 0.f);
    acc.y = fmaxf(acc.y + bb.y, 0.f);
    acc.z = fmaxf(acc.z + bb.z, 0.f);
    acc.w = fmaxf(acc.w + bb.w, 0.f);
    *(float4*)(g_hidden + (size_t)node * HH + lane * 4) = acc;
}

// ---------------- aggregation 2 ----------------
__global__ __launch_bounds__(256) void agg2_bias_kernel(
    const float* __restrict__ b2, const float* __restrict__ b3,
    float* __restrict__ out_mu, float* __restrict__ out_lv)
{
    int node = blockIdx.x * 8 + (threadIdx.x >> 5);
    int lane = threadIdx.x & 31;
    int s = g_rowstart[node];
    int e = g_rowstart[node + 1];
    float4 acc = make_float4(0.f, 0.f, 0.f, 0.f);
    int j = s;
    for (; j + 4 <= e; j += 4) {
        int i0 = g_csr[j + 0], i1 = g_csr[j + 1], i2 = g_csr[j + 2], i3 = g_csr[j + 3];
        float4 v0 = *(const float4*)(g_P + (size_t)i0 * P2 + lane * 4);
        float4 v1 = *(const float4*)(g_P + (size_t)i1 * P2 + lane * 4);
        float4 v2 = *(const float4*)(g_P + (size_t)i2 * P2 + lane * 4);
        float4 v3 = *(const float4*)(g_P + (size_t)i3 * P2 + lane * 4);
        acc.x += v0.x + v1.x + v2.x + v3.x;
        acc.y += v0.y + v1.y + v2.y + v3.y;
        acc.z += v0.z + v1.z + v2.z + v3.z;
        acc.w += v0.w + v1.w + v2.w + v3.w;
    }
    for (; j < e; j++) {
        int i0 = g_csr[j];
        float4 v0 = *(const float4*)(g_P + (size_t)i0 * P2 + lane * 4);
        acc.x += v0.x; acc.y += v0.y; acc.z += v0.z; acc.w += v0.w;
    }
    if (lane < 16) {
        float4 bb = ((const float4*)b2)[lane];
        acc.x += bb.x; acc.y += bb.y; acc.z += bb.z; acc.w += bb.w;
        *(float4*)(out_mu + (size_t)node * LL + lane * 4) = acc;
    } else {
        float4 bb = ((const float4*)b3)[lane - 16];
        acc.x += bb.x; acc.y += bb.y; acc.z += bb.z; acc.w += bb.w;
        *(float4*)(out_lv + (size_t)node * LL + (lane - 16) * 4) = acc;
    }
}

// ---------------- split z -> (hi, lo) concatenated bf16 operands ----------------
__global__ __launch_bounds__(256) void split_kernel(const float* __restrict__ z) {
    int i = blockIdx.x * blockDim.x + threadIdx.x;   // over NN*LL
    int m = i >> 6;
    int k = i & 63;
    float v = z[i];
    __nv_bfloat16 h = __float2bfloat16(v);
    __nv_bfloat16 l = __float2bfloat16(v - __bfloat162float(h));
    __nv_bfloat16* a = g_Acat + (size_t)m * 192;
    __nv_bfloat16* b = g_Bcat + (size_t)m * 192;
    a[k] = h;  a[64 + k] = h;  a[128 + k] = l;
    b[k] = h;  b[64 + k] = l;  b[128 + k] = h;
}

// ---------------- adj = sigmoid(Z @ Z^T) via mma.sync bf16 (split, K=192) ----------------
__device__ __forceinline__ float sigmoid_tanh(float x) {
    float t;
    asm("tanh.approx.f32 %0, %1;" : "=f"(t) : "f"(0.5f * x));
    return 0.5f * t + 0.5f;
}

// CTA 128x128, 4 warps of 64x64 each, K=192 resident. Rows padded to 200 bf16.
#define G3_PAD   200
#define G3_ASZ   (128 * G3_PAD * 2)
#define G3_SMEM  (2 * G3_ASZ)

__global__ __launch_bounds__(128, 2) void gemm3_mma_kernel(float* __restrict__ adj)
{
    extern __shared__ __align__(16) char smem[];
    __nv_bfloat16* sA = (__nv_bfloat16*)smem;
    __nv_bfloat16* sB = (__nv_bfloat16*)(smem + G3_ASZ);

    int tid  = threadIdx.x;
    int lane = tid & 31;
    int w    = tid >> 5;
    int m0 = blockIdx.y * 128;
    int n0 = blockIdx.x * 128;

    // cooperative tile load: 2 tiles x 128 rows x 24 uint4 (192 bf16/row)
    for (int i = tid; i < 2 * 128 * 24; i += 128) {
        int t   = (i >= 3072);
        int j   = t ? i - 3072 : i;
        int row = j / 24;
        int u   = j % 24;
        const __nv_bfloat16* g =
            (t ? g_Bcat + (size_t)(n0 + row) * 192
               : g_Acat + (size_t)(m0 + row) * 192) + u * 8;
        __nv_bfloat16* d = (t ? sB : sA) + row * G3_PAD + u * 8;
        *(uint4*)d = *(const uint4*)g;
    }
    __syncthreads();

    // warp tiling: 2x2 warps, each 64 (m) x 64 (n)
    int wm = (w >> 1) * 64;
    int wn = (w & 1) * 64;
    int grp = lane >> 2;       // 0..7
    int qid = lane & 3;        // 0..3

    float acc[4][8][4];
#pragma unroll
    for (int mt = 0; mt < 4; mt++)
#pragma unroll
        for (int nt = 0; nt < 8; nt++)
#pragma unroll
            for (int r = 0; r < 4; r++) acc[mt][nt][r] = 0.f;

#pragma unroll
    for (int ks = 0; ks < 12; ks++) {
        int k0 = ks * 16 + qid * 2;
        uint32_t a[4][4], b[8][2];
#pragma unroll
        for (int mt = 0; mt < 4; mt++) {
            const __nv_bfloat16* base = sA + (wm + mt * 16 + grp) * G3_PAD;
            a[mt][0] = *(const uint32_t*)(base + k0);
            a[mt][1] = *(const uint32_t*)(base + 8 * G3_PAD + k0);
            a[mt][2] = *(const uint32_t*)(base + k0 + 8);
            a[mt][3] = *(const uint32_t*)(base + 8 * G3_PAD + k0 + 8);
        }
#pragma unroll
        for (int nt = 0; nt < 8; nt++) {
            const __nv_bfloat16* base = sB + (wn + nt * 8 + grp) * G3_PAD;
            b[nt][0] = *(const uint32_t*)(base + k0);
            b[nt][1] = *(const uint32_t*)(base + k0 + 8);
        }
#pragma unroll
        for (int mt = 0; mt < 4; mt++)
#pragma unroll
            for (int nt = 0; nt < 8; nt++)
                mma_bf16(acc[mt][nt], a[mt], b[nt]);
    }

    // epilogue: sigmoid + direct stores
#pragma unroll
    for (int mt = 0; mt < 4; mt++) {
        int row = m0 + wm + mt * 16 + grp;
#pragma unroll
        for (int nt = 0; nt < 8; nt++) {
            int col = n0 + wn + nt * 8 + qid * 2;
            float2 v0, v1;
            v0.x = sigmoid_tanh(acc[mt][nt][0]);
            v0.y = sigmoid_tanh(acc[mt][nt][1]);
            v1.x = sigmoid_tanh(acc[mt][nt][2]);
            v1.y = sigmoid_tanh(acc[mt][nt][3]);
            *(float2*)(adj + (size_t)row * NN + col)       = v0;
            *(float2*)(adj + (size_t)(row + 8) * NN + col) = v1;
        }
    }
}

// ---------------- launch ----------------
extern "C" void kernel_launch(void* const* d_in, const int* in_sizes, int n_in,
                              void* d_out, int out_size)
{
    const float* features = (const float*)d_in[0];
    const int*   src      = (const int*)  d_in[1];
    const int*   dst      = (const int*)  d_in[2];
    const float* W1       = (const float*)d_in[3];
    const float* b1       = (const float*)d_in[4];
    const float* W2       = (const float*)d_in[5];
    const float* b2       = (const float*)d_in[6];
    const float* W3       = (const float*)d_in[7];
    const float* b3       = (const float*)d_in[8];

    float* adj = (float*)d_out;
    float* mu  = adj + (size_t)NN * NN;
    float* lv  = mu  + (size_t)NN * LL;

    float *x1p, *hidp, *pp;
    cudaGetSymbolAddress((void**)&x1p,  g_X1);
    cudaGetSymbolAddress((void**)&hidp, g_hidden);
    cudaGetSymbolAddress((void**)&pp,   g_P);

    __nv_bfloat16 *fhi, *flo, *w1hi, *w1lo, *hhi, *hlo, *wchi, *wclo;
    cudaGetSymbolAddress((void**)&fhi,  g_fhi);
    cudaGetSymbolAddress((void**)&flo,  g_flo);
    cudaGetSymbolAddress((void**)&w1hi, g_w1hi);
    cudaGetSymbolAddress((void**)&w1lo, g_w1lo);
    cudaGetSymbolAddress((void**)&hhi,  g_hhi);
    cudaGetSymbolAddress((void**)&hlo,  g_hlo);
    cudaGetSymbolAddress((void**)&wchi, g_wchi);
    cudaGetSymbolAddress((void**)&wclo, g_wclo);

    cudaFuncSetAttribute(gemm3_mma_kernel,
                         cudaFuncAttributeMaxDynamicSharedMemorySize, G3_SMEM);
    cudaFuncSetAttribute(gemm12_kernel,
                         cudaFuncAttributeMaxDynamicSharedMemorySize, G12_SMEM);

    // CSR build
    zero_counts_kernel<<<NN / 256, 256>>>();
    count_kernel<<<EE / 256, 256>>>(dst);
    scan_kernel<<<1, 256>>>();
    fill_kernel<<<EE / 256, 256>>>(src, dst);

    // split features and weights into bf16 hi/lo
    conv_split_kernel<<<(NN * FIN / 4) / 256, 256>>>(features, fhi, flo, NN * FIN / 4);
    conv_split_kernel<<<(HH * FIN / 4) / 256, 256>>>(W1, w1hi, w1lo, HH * FIN / 4);
    conv_split_kernel<<<(LL * HH / 4) / 256, 256>>>(W2, wchi, wclo, LL * HH / 4);
    conv_split_kernel<<<(LL * HH / 4) / 256, 256>>>(W3, wchi + (size_t)LL * HH,
                                                    wclo + (size_t)LL * HH, LL * HH / 4);

    // X1 = features @ W1^T   [8192,256]  (split-bf16 tensor GEMM)
    gemm12_kernel<<<dim3(HH / 64, NN / 128), 256, G12_SMEM>>>(
        fhi, flo, w1hi, w1lo, x1p, HH, FIN);

    // hidden = relu(segsum(X1) + b1)
    agg1_relu_kernel<<<NN / 4, 256>>>(b1);

    // split hidden into bf16 hi/lo
    conv_split_kernel<<<(NN * HH / 4) / 256, 256>>>(hidp, hhi, hlo, NN * HH / 4);

    // P = hidden @ [W2;W3]^T   [8192,128]  (split-bf16 tensor GEMM)
    gemm12_kernel<<<dim3(P2 / 64, NN / 128), 256, G12_SMEM>>>(
        hhi, hlo, wchi, wclo, pp, P2, HH);

    // mu / logvar = segsum(P) + b2/b3   (written straight into d_out)
    agg2_bias_kernel<<<NN / 8, 256>>>(b2, b3, mu, lv);

    // split z = mu into bf16 hi/lo concatenated operands
    split_kernel<<<(NN * LL) / 256, 256>>>(mu);

    // adj = sigmoid(Z @ Z^T) via mma.sync split-bf16, K=192
    gemm3_mma_kernel<<<dim3(NN / 128, NN / 128), 128, G3_SMEM>>>(adj);
}

// round 5
// speedup vs baseline: 1.8908x; 1.2016x over previous
#include <cuda_runtime.h>
#include <cuda_bf16.h>
#include <cstdint>

// Problem constants (match reference)
#define NN    8192        // nodes
#define EE    262144      // edges
#define FIN   512
#define HH    256
#define LL    64
#define P2    128         // 2*L (W2 and W3 concatenated)

// ---------------- device scratch (no allocation allowed) ----------------
__device__ float g_X1[NN * HH];        // features @ W1^T          [N,256]
__device__ float g_hidden[NN * HH];    // relu(agg1 + b1)          [N,256]
__device__ float g_P[NN * P2];         // hidden @ [W2;W3]^T       [N,128]
__device__ int   g_cnt[NN];
__device__ int   g_rowstart[NN + 1];
__device__ int   g_cursor[NN];
__device__ int   g_csr[EE];            // src indices grouped by dst

// split-bf16 operand buffers
__device__ __align__(256) __nv_bfloat16 g_fhi[NN * FIN];   // features hi
__device__ __align__(256) __nv_bfloat16 g_flo[NN * FIN];   // features lo
__device__ __align__(256) __nv_bfloat16 g_w1hi[HH * FIN];
__device__ __align__(256) __nv_bfloat16 g_w1lo[HH * FIN];
__device__ __align__(256) __nv_bfloat16 g_hhi[NN * HH];    // hidden hi
__device__ __align__(256) __nv_bfloat16 g_hlo[NN * HH];
__device__ __align__(256) __nv_bfloat16 g_wchi[P2 * HH];   // [W2;W3] hi
__device__ __align__(256) __nv_bfloat16 g_wclo[P2 * HH];

// split-bf16 concatenated operands for the adj GEMM (K = 3*64 = 192)
// A_cat[m] = [hi, hi, lo],  B_cat[n] = [hi, lo, hi]
__device__ __align__(256) __nv_bfloat16 g_Acat[NN * 192];
__device__ __align__(256) __nv_bfloat16 g_Bcat[NN * 192];

// ---------------- CSR build ----------------
__global__ void zero_counts_kernel() {
    int i = blockIdx.x * blockDim.x + threadIdx.x;
    if (i < NN) g_cnt[i] = 0;
}

__global__ void count_kernel(const int* __restrict__ dst) {
    int e = blockIdx.x * blockDim.x + threadIdx.x;
    if (e < EE) atomicAdd(&g_cnt[dst[e]], 1);
}

__global__ void scan_kernel() {
    __shared__ int ssum[256];
    int t = threadIdx.x;
    int base = t * 32;
    int vals[32];
    int s = 0;
#pragma unroll
    for (int j = 0; j < 32; j++) { vals[j] = g_cnt[base + j]; s += vals[j]; }
    ssum[t] = s;
    __syncthreads();
#pragma unroll
    for (int off = 1; off < 256; off <<= 1) {
        int v = (t >= off) ? ssum[t - off] : 0;
        __syncthreads();
        ssum[t] += v;
        __syncthreads();
    }
    int run = ssum[t] - s;
#pragma unroll
    for (int j = 0; j < 32; j++) {
        g_rowstart[base + j] = run;
        g_cursor[base + j]   = run;
        run += vals[j];
    }
    if (t == 255) g_rowstart[NN] = run;
}

__global__ void fill_kernel(const int* __restrict__ src, const int* __restrict__ dst) {
    int e = blockIdx.x * blockDim.x + threadIdx.x;
    if (e < EE) {
        int d = dst[e];
        int pos = atomicAdd(&g_cursor[d], 1);
        g_csr[pos] = src[e];
    }
}

// ---------------- fp32 -> bf16 hi/lo split (vectorized float4) ----------------
__global__ void conv_split_kernel(const float* __restrict__ in,
                                  __nv_bfloat16* __restrict__ hi,
                                  __nv_bfloat16* __restrict__ lo, int n4)
{
    int i = blockIdx.x * blockDim.x + threadIdx.x;
    if (i >= n4) return;
    float4 v = ((const float4*)in)[i];
    __nv_bfloat16 h0 = __float2bfloat16(v.x);
    __nv_bfloat16 h1 = __float2bfloat16(v.y);
    __nv_bfloat16 h2 = __float2bfloat16(v.z);
    __nv_bfloat16 h3 = __float2bfloat16(v.w);
    __nv_bfloat16 l0 = __float2bfloat16(v.x - __bfloat162float(h0));
    __nv_bfloat16 l1 = __float2bfloat16(v.y - __bfloat162float(h1));
    __nv_bfloat16 l2 = __float2bfloat16(v.z - __bfloat162float(h2));
    __nv_bfloat16 l3 = __float2bfloat16(v.w - __bfloat162float(h3));
    __nv_bfloat162* hp = (__nv_bfloat162*)(hi + i * 4);
    __nv_bfloat162* lp = (__nv_bfloat162*)(lo + i * 4);
    hp[0] = __nv_bfloat162(h0, h1);
    hp[1] = __nv_bfloat162(h2, h3);
    lp[0] = __nv_bfloat162(l0, l1);
    lp[1] = __nv_bfloat162(l2, l3);
}

// ---------------- bf16 mma primitive ----------------
__device__ __forceinline__ void mma_bf16(
    float* c, const uint32_t* a, const uint32_t* b)
{
    asm volatile(
        "mma.sync.aligned.m16n8k16.row.col.f32.bf16.bf16.f32 "
        "{%0,%1,%2,%3}, {%4,%5,%6,%7}, {%8,%9}, {%0,%1,%2,%3};"
        : "+f"(c[0]), "+f"(c[1]), "+f"(c[2]), "+f"(c[3])
        : "r"(a[0]), "r"(a[1]), "r"(a[2]), "r"(a[3]), "r"(b[0]), "r"(b[1]));
}

#define LDMATRIX_X4(r0, r1, r2, r3, addr) \
    asm volatile("ldmatrix.sync.aligned.m8n8.x4.shared.b16 {%0,%1,%2,%3}, [%4];" \
        : "=r"(r0), "=r"(r1), "=r"(r2), "=r"(r3) : "r"(addr))

// ---------------- split-bf16 GEMM: C[M,Nd] = (Ahi+Alo)[M,K] @ (Bhi+Blo)[Nd,K]^T ----
// (drops lo*lo term). CTA 128x64, 8 warps of 32x32, BK=64, smem rows padded to 72.
#define G12_SMEM ((128 * 72 + 64 * 72) * 2 * 2)   // 55296 B

__global__ __launch_bounds__(256) void gemm12_kernel(
    const __nv_bfloat16* __restrict__ Ahi, const __nv_bfloat16* __restrict__ Alo,
    const __nv_bfloat16* __restrict__ Bhi, const __nv_bfloat16* __restrict__ Blo,
    float* __restrict__ C, int Nd, int K)
{
    extern __shared__ __align__(16) char sm12[];
    __nv_bfloat16* sAh = (__nv_bfloat16*)sm12;        // 128*72
    __nv_bfloat16* sAl = sAh + 128 * 72;
    __nv_bfloat16* sBh = sAl + 128 * 72;              // 64*72
    __nv_bfloat16* sBl = sBh + 64 * 72;

    int tid  = threadIdx.x;
    int lane = tid & 31;
    int w    = tid >> 5;
    int wm = (w >> 1) * 32;
    int wn = (w & 1) * 32;
    int grp = lane >> 2;
    int qid = lane & 3;
    int m0 = blockIdx.y * 128;
    int n0 = blockIdx.x * 64;

    float acc[2][4][4];
#pragma unroll
    for (int mt = 0; mt < 2; mt++)
#pragma unroll
        for (int nt = 0; nt < 4; nt++)
#pragma unroll
            for (int r = 0; r < 4; r++) acc[mt][nt][r] = 0.f;

    for (int kt = 0; kt < K; kt += 64) {
#pragma unroll
        for (int it = 0; it < 4; it++) {
            int i = it * 256 + tid;
            int row = i >> 3, u = i & 7;
            size_t go = (size_t)(m0 + row) * K + kt + u * 8;
            int so = row * 72 + u * 8;
            *(uint4*)(sAh + so) = *(const uint4*)(Ahi + go);
            *(uint4*)(sAl + so) = *(const uint4*)(Alo + go);
        }
#pragma unroll
        for (int it = 0; it < 2; it++) {
            int i = it * 256 + tid;
            int row = i >> 3, u = i & 7;
            size_t go = (size_t)(n0 + row) * K + kt + u * 8;
            int so = row * 72 + u * 8;
            *(uint4*)(sBh + so) = *(const uint4*)(Bhi + go);
            *(uint4*)(sBl + so) = *(const uint4*)(Blo + go);
        }
        __syncthreads();
#pragma unroll
        for (int ks = 0; ks < 4; ks++) {
            int k0 = ks * 16 + qid * 2;
            uint32_t ah[2][4], al[2][4], bh[4][2], bl[4][2];
#pragma unroll
            for (int mt = 0; mt < 2; mt++) {
                const __nv_bfloat16* p = sAh + (wm + mt * 16 + grp) * 72 + k0;
                ah[mt][0] = *(const uint32_t*)(p);
                ah[mt][1] = *(const uint32_t*)(p + 8 * 72);
                ah[mt][2] = *(const uint32_t*)(p + 8);
                ah[mt][3] = *(const uint32_t*)(p + 8 * 72 + 8);
                const __nv_bfloat16* q = sAl + (wm + mt * 16 + grp) * 72 + k0;
                al[mt][0] = *(const uint32_t*)(q);
                al[mt][1] = *(const uint32_t*)(q + 8 * 72);
                al[mt][2] = *(const uint32_t*)(q + 8);
                al[mt][3] = *(const uint32_t*)(q + 8 * 72 + 8);
            }
#pragma unroll
            for (int nt = 0; nt < 4; nt++) {
                const __nv_bfloat16* p = sBh + (wn + nt * 8 + grp) * 72 + k0;
                bh[nt][0] = *(const uint32_t*)(p);
                bh[nt][1] = *(const uint32_t*)(p + 8);
                const __nv_bfloat16* q = sBl + (wn + nt * 8 + grp) * 72 + k0;
                bl[nt][0] = *(const uint32_t*)(q);
                bl[nt][1] = *(const uint32_t*)(q + 8);
            }
#pragma unroll
            for (int mt = 0; mt < 2; mt++)
#pragma unroll
                for (int nt = 0; nt < 4; nt++) {
                    mma_bf16(acc[mt][nt], ah[mt], bh[nt]);
                    mma_bf16(acc[mt][nt], ah[mt], bl[nt]);
                    mma_bf16(acc[mt][nt], al[mt], bh[nt]);
                }
        }
        __syncthreads();
    }

#pragma unroll
    for (int mt = 0; mt < 2; mt++) {
        int row = m0 + wm + mt * 16 + grp;
#pragma unroll
        for (int nt = 0; nt < 4; nt++) {
            int col = n0 + wn + nt * 8 + qid * 2;
            float2 v0 = make_float2(acc[mt][nt][0], acc[mt][nt][1]);
            float2 v1 = make_float2(acc[mt][nt][2], acc[mt][nt][3]);
            *(float2*)(C + (size_t)row * Nd + col)       = v0;
            *(float2*)(C + (size_t)(row + 8) * Nd + col) = v1;
        }
    }
}

// ---------------- aggregation 1 ----------------
__global__ __launch_bounds__(256) void agg1_relu_kernel(const float* __restrict__ b1) {
    int node = blockIdx.x * 4 + (threadIdx.x >> 6);
    int lane = threadIdx.x & 63;
    int s = g_rowstart[node];
    int e = g_rowstart[node + 1];
    float4 acc = make_float4(0.f, 0.f, 0.f, 0.f);
    int j = s;
    for (; j + 4 <= e; j += 4) {
        int i0 = g_csr[j + 0], i1 = g_csr[j + 1], i2 = g_csr[j + 2], i3 = g_csr[j + 3];
        float4 v0 = *(const float4*)(g_X1 + (size_t)i0 * HH + lane * 4);
        float4 v1 = *(const float4*)(g_X1 + (size_t)i1 * HH + lane * 4);
        float4 v2 = *(const float4*)(g_X1 + (size_t)i2 * HH + lane * 4);
        float4 v3 = *(const float4*)(g_X1 + (size_t)i3 * HH + lane * 4);
        acc.x += v0.x + v1.x + v2.x + v3.x;
        acc.y += v0.y + v1.y + v2.y + v3.y;
        acc.z += v0.z + v1.z + v2.z + v3.z;
        acc.w += v0.w + v1.w + v2.w + v3.w;
    }
    for (; j < e; j++) {
        int i0 = g_csr[j];
        float4 v0 = *(const float4*)(g_X1 + (size_t)i0 * HH + lane * 4);
        acc.x += v0.x; acc.y += v0.y; acc.z += v0.z; acc.w += v0.w;
    }
    float4 bb = ((const float4*)b1)[lane];
    acc.x = fmaxf(acc.x + bb.x, 0.f);
    acc.y = fmaxf(acc.y + bb.y, 0.f);
    acc.z = fmaxf(acc.z + bb.z, 0.f);
    acc.w = fmaxf(acc.w + bb.w, 0.f);
    *(float4*)(g_hidden + (size_t)node * HH + lane * 4) = acc;
}

// ---------------- aggregation 2 ----------------
__global__ __launch_bounds__(256) void agg2_bias_kernel(
    const float* __restrict__ b2, const float* __restrict__ b3,
    float* __restrict__ out_mu, float* __restrict__ out_lv)
{
    int node = blockIdx.x * 8 + (threadIdx.x >> 5);
    int lane = threadIdx.x & 31;
    int s = g_rowstart[node];
    int e = g_rowstart[node + 1];
    float4 acc = make_float4(0.f, 0.f, 0.f, 0.f);
    int j = s;
    for (; j + 4 <= e; j += 4) {
        int i0 = g_csr[j + 0], i1 = g_csr[j + 1], i2 = g_csr[j + 2], i3 = g_csr[j + 3];
        float4 v0 = *(const float4*)(g_P + (size_t)i0 * P2 + lane * 4);
        float4 v1 = *(const float4*)(g_P + (size_t)i1 * P2 + lane * 4);
        float4 v2 = *(const float4*)(g_P + (size_t)i2 * P2 + lane * 4);
        float4 v3 = *(const float4*)(g_P + (size_t)i3 * P2 + lane * 4);
        acc.x += v0.x + v1.x + v2.x + v3.x;
        acc.y += v0.y + v1.y + v2.y + v3.y;
        acc.z += v0.z + v1.z + v2.z + v3.z;
        acc.w += v0.w + v1.w + v2.w + v3.w;
    }
    for (; j < e; j++) {
        int i0 = g_csr[j];
        float4 v0 = *(const float4*)(g_P + (size_t)i0 * P2 + lane * 4);
        acc.x += v0.x; acc.y += v0.y; acc.z += v0.z; acc.w += v0.w;
    }
    if (lane < 16) {
        float4 bb = ((const float4*)b2)[lane];
        acc.x += bb.x; acc.y += bb.y; acc.z += bb.z; acc.w += bb.w;
        *(float4*)(out_mu + (size_t)node * LL + lane * 4) = acc;
    } else {
        float4 bb = ((const float4*)b3)[lane - 16];
        acc.x += bb.x; acc.y += bb.y; acc.z += bb.z; acc.w += bb.w;
        *(float4*)(out_lv + (size_t)node * LL + (lane - 16) * 4) = acc;
    }
}

// ---------------- split z -> (hi, lo) concatenated bf16 operands ----------------
__global__ __launch_bounds__(256) void split_kernel(const float* __restrict__ z) {
    int i = blockIdx.x * blockDim.x + threadIdx.x;   // over NN*LL
    int m = i >> 6;
    int k = i & 63;
    float v = z[i];
    __nv_bfloat16 h = __float2bfloat16(v);
    __nv_bfloat16 l = __float2bfloat16(v - __bfloat162float(h));
    __nv_bfloat16* a = g_Acat + (size_t)m * 192;
    __nv_bfloat16* b = g_Bcat + (size_t)m * 192;
    a[k] = h;  a[64 + k] = h;  a[128 + k] = l;
    b[k] = h;  b[64 + k] = l;  b[128 + k] = h;
}

// ---------------- adj = sigmoid(Z @ Z^T) via mma.sync bf16 (split, K=192) ----------------
__device__ __forceinline__ float sigmoid_tanh(float x) {
    float t;
    asm("tanh.approx.f32 %0, %1;" : "=f"(t) : "f"(0.5f * x));
    return 0.5f * t + 0.5f;
}

// CTA 128x128, 4 warps of 64x64 each, K=192 resident. Rows padded to 200 bf16.
// Symmetric output: only lower-triangle blocks computed; off-diagonal blocks
// mirror-write the transposed tile.
#define G3_PAD   200
#define G3_ASZ   (128 * G3_PAD * 2)
#define G3_SMEM  (2 * G3_ASZ)

__global__ __launch_bounds__(128, 2) void gemm3_mma_kernel(float* __restrict__ adj)
{
    if (blockIdx.x > blockIdx.y) return;   // symmetry: skip upper-triangle blocks

    extern __shared__ __align__(16) char smem[];
    __nv_bfloat16* sA = (__nv_bfloat16*)smem;
    __nv_bfloat16* sB = (__nv_bfloat16*)(smem + G3_ASZ);

    int tid  = threadIdx.x;
    int lane = tid & 31;
    int w    = tid >> 5;
    int m0 = blockIdx.y * 128;
    int n0 = blockIdx.x * 128;
    bool diag = (blockIdx.x == blockIdx.y);

    // cooperative tile load: 2 tiles x 128 rows x 24 uint4 (192 bf16/row)
    for (int i = tid; i < 2 * 128 * 24; i += 128) {
        int t   = (i >= 3072);
        int j   = t ? i - 3072 : i;
        int row = j / 24;
        int u   = j % 24;
        const __nv_bfloat16* g =
            (t ? g_Bcat + (size_t)(n0 + row) * 192
               : g_Acat + (size_t)(m0 + row) * 192) + u * 8;
        __nv_bfloat16* d = (t ? sB : sA) + row * G3_PAD + u * 8;
        *(uint4*)d = *(const uint4*)g;
    }
    __syncthreads();

    // warp tiling: 2x2 warps, each 64 (m) x 64 (n)
    int wm = (w >> 1) * 64;
    int wn = (w & 1) * 64;
    int grp = lane >> 2;       // 0..7
    int qid = lane & 3;        // 0..3

    // ldmatrix lane-dependent base addresses
    uint32_t sA32 = (uint32_t)__cvta_generic_to_shared(sA);
    uint32_t sB32 = (uint32_t)__cvta_generic_to_shared(sB);
    int a_row = (lane & 7) + ((lane >> 3) & 1) * 8;   // tiles: r0-7/r8-15 x k0/k16B
    int a_cb  = (lane >> 4) * 16;
    int b_row = (lane & 7) + ((lane >> 4) & 1) * 8;   // tiles: n-pair x k0/k16B
    int b_cb  = ((lane >> 3) & 1) * 16;
    uint32_t a_addr[4], b_addr[4];
#pragma unroll
    for (int mt = 0; mt < 4; mt++)
        a_addr[mt] = sA32 + (uint32_t)(wm + mt * 16 + a_row) * (G3_PAD * 2) + a_cb;
#pragma unroll
    for (int np = 0; np < 4; np++)
        b_addr[np] = sB32 + (uint32_t)(wn + np * 16 + b_row) * (G3_PAD * 2) + b_cb;

    float acc[4][8][4];
#pragma unroll
    for (int mt = 0; mt < 4; mt++)
#pragma unroll
        for (int nt = 0; nt < 8; nt++)
#pragma unroll
            for (int r = 0; r < 4; r++) acc[mt][nt][r] = 0.f;

#pragma unroll
    for (int ks = 0; ks < 12; ks++) {
        uint32_t koff = ks * 32;           // 16 bf16 = 32 bytes
        uint32_t a[4][4], b[8][2];
#pragma unroll
        for (int mt = 0; mt < 4; mt++)
            LDMATRIX_X4(a[mt][0], a[mt][1], a[mt][2], a[mt][3], a_addr[mt] + koff);
#pragma unroll
        for (int np = 0; np < 4; np++)
            LDMATRIX_X4(b[2 * np][0], b[2 * np][1], b[2 * np + 1][0], b[2 * np + 1][1],
                        b_addr[np] + koff);
#pragma unroll
        for (int mt = 0; mt < 4; mt++)
#pragma unroll
            for (int nt = 0; nt < 8; nt++)
                mma_bf16(acc[mt][nt], a[mt], b[nt]);
    }

    // epilogue: sigmoid + direct stores (+ mirrored transposed stores off-diagonal)
#pragma unroll
    for (int mt = 0; mt < 4; mt++) {
        int row = m0 + wm + mt * 16 + grp;
#pragma unroll
        for (int nt = 0; nt < 8; nt++) {
            int col = n0 + wn + nt * 8 + qid * 2;
            float s0 = sigmoid_tanh(acc[mt][nt][0]);
            float s1 = sigmoid_tanh(acc[mt][nt][1]);
            float s2 = sigmoid_tanh(acc[mt][nt][2]);
            float s3 = sigmoid_tanh(acc[mt][nt][3]);
            *(float2*)(adj + (size_t)row * NN + col)       = make_float2(s0, s1);
            *(float2*)(adj + (size_t)(row + 8) * NN + col) = make_float2(s2, s3);
            if (!diag) {
                adj[(size_t)col * NN + row]           = s0;
                adj[(size_t)(col + 1) * NN + row]     = s1;
                adj[(size_t)col * NN + row + 8]       = s2;
                adj[(size_t)(col + 1) * NN + row + 8] = s3;
            }
        }
    }
}

// ---------------- launch ----------------
extern "C" void kernel_launch(void* const* d_in, const int* in_sizes, int n_in,
                              void* d_out, int out_size)
{
    const float* features = (const float*)d_in[0];
    const int*   src      = (const int*)  d_in[1];
    const int*   dst      = (const int*)  d_in[2];
    const float* W1       = (const float*)d_in[3];
    const float* b1       = (const float*)d_in[4];
    const float* W2       = (const float*)d_in[5];
    const float* b2       = (const float*)d_in[6];
    const float* W3       = (const float*)d_in[7];
    const float* b3       = (const float*)d_in[8];

    float* adj = (float*)d_out;
    float* mu  = adj + (size_t)NN * NN;
    float* lv  = mu  + (size_t)NN * LL;

    float *x1p, *hidp, *pp;
    cudaGetSymbolAddress((void**)&x1p,  g_X1);
    cudaGetSymbolAddress((void**)&hidp, g_hidden);
    cudaGetSymbolAddress((void**)&pp,   g_P);

    __nv_bfloat16 *fhi, *flo, *w1hi, *w1lo, *hhi, *hlo, *wchi, *wclo;
    cudaGetSymbolAddress((void**)&fhi,  g_fhi);
    cudaGetSymbolAddress((void**)&flo,  g_flo);
    cudaGetSymbolAddress((void**)&w1hi, g_w1hi);
    cudaGetSymbolAddress((void**)&w1lo, g_w1lo);
    cudaGetSymbolAddress((void**)&hhi,  g_hhi);
    cudaGetSymbolAddress((void**)&hlo,  g_hlo);
    cudaGetSymbolAddress((void**)&wchi, g_wchi);
    cudaGetSymbolAddress((void**)&wclo, g_wclo);

    cudaFuncSetAttribute(gemm3_mma_kernel,
                         cudaFuncAttributeMaxDynamicSharedMemorySize, G3_SMEM);
    cudaFuncSetAttribute(gemm12_kernel,
                         cudaFuncAttributeMaxDynamicSharedMemorySize, G12_SMEM);

    // CSR build
    zero_counts_kernel<<<NN / 256, 256>>>();
    count_kernel<<<EE / 256, 256>>>(dst);
    scan_kernel<<<1, 256>>>();
    fill_kernel<<<EE / 256, 256>>>(src, dst);

    // split features and weights into bf16 hi/lo
    conv_split_kernel<<<(NN * FIN / 4) / 256, 256>>>(features, fhi, flo, NN * FIN / 4);
    conv_split_kernel<<<(HH * FIN / 4) / 256, 256>>>(W1, w1hi, w1lo, HH * FIN / 4);
    conv_split_kernel<<<(LL * HH / 4) / 256, 256>>>(W2, wchi, wclo, LL * HH / 4);
    conv_split_kernel<<<(LL * HH / 4) / 256, 256>>>(W3, wchi + (size_t)LL * HH,
                                                    wclo + (size_t)LL * HH, LL * HH / 4);

    // X1 = features @ W1^T   [8192,256]  (split-bf16 tensor GEMM)
    gemm12_kernel<<<dim3(HH / 64, NN / 128), 256, G12_SMEM>>>(
        fhi, flo, w1hi, w1lo, x1p, HH, FIN);

    // hidden = relu(segsum(X1) + b1)
    agg1_relu_kernel<<<NN / 4, 256>>>(b1);

    // split hidden into bf16 hi/lo
    conv_split_kernel<<<(NN * HH / 4) / 256, 256>>>(hidp, hhi, hlo, NN * HH / 4);

    // P = hidden @ [W2;W3]^T   [8192,128]  (split-bf16 tensor GEMM)
    gemm12_kernel<<<dim3(P2 / 64, NN / 128), 256, G12_SMEM>>>(
        hhi, hlo, wchi, wclo, pp, P2, HH);

    // mu / logvar = segsum(P) + b2/b3   (written straight into d_out)
    agg2_bias_kernel<<<NN / 8, 256>>>(b2, b3, mu, lv);

    // split z = mu into bf16 hi/lo concatenated operands
    split_kernel<<<(NN * LL) / 256, 256>>>(mu);

    // adj = sigmoid(Z @ Z^T) via mma.sync split-bf16, K=192, symmetric
    gemm3_mma_kernel<<<dim3(NN / 128, NN / 128), 128, G3_SMEM>>>(adj);
}

// round 6
// speedup vs baseline: 1.9499x; 1.0312x over previous
#include <cuda_runtime.h>
#include <cuda_bf16.h>
#include <cstdint>

// Problem constants (match reference)
#define NN    8192        // nodes
#define EE    262144      // edges
#define FIN   512
#define HH    256
#define LL    64
#define P2    128         // 2*L (W2 and W3 concatenated)

// ---------------- device scratch (no allocation allowed) ----------------
__device__ float g_X1[NN * HH];        // features @ W1^T          [N,256]
__device__ float g_P[NN * P2];         // hidden @ [W2;W3]^T       [N,128]
__device__ int   g_cnt[NN];
__device__ int   g_rowstart[NN + 1];
__device__ int   g_cursor[NN];
__device__ int   g_csr[EE];            // src indices grouped by dst

// split-bf16 operand buffers
__device__ __align__(256) __nv_bfloat16 g_fhi[NN * FIN];   // features hi
__device__ __align__(256) __nv_bfloat16 g_flo[NN * FIN];   // features lo
__device__ __align__(256) __nv_bfloat16 g_w1hi[HH * FIN];
__device__ __align__(256) __nv_bfloat16 g_w1lo[HH * FIN];
__device__ __align__(256) __nv_bfloat16 g_hhi[NN * HH];    // hidden hi
__device__ __align__(256) __nv_bfloat16 g_hlo[NN * HH];
__device__ __align__(256) __nv_bfloat16 g_wchi[P2 * HH];   // [W2;W3] hi
__device__ __align__(256) __nv_bfloat16 g_wclo[P2 * HH];

// split-bf16 concatenated operands for the adj GEMM (K = 3*64 = 192)
// A_cat[m] = [hi, hi, lo],  B_cat[n] = [hi, lo, hi]
__device__ __align__(256) __nv_bfloat16 g_Acat[NN * 192];
__device__ __align__(256) __nv_bfloat16 g_Bcat[NN * 192];

// ---------------- CSR build ----------------
__global__ void zero_counts_kernel() {
    int i = blockIdx.x * blockDim.x + threadIdx.x;
    if (i < NN) g_cnt[i] = 0;
}

// 4 edges per thread for memory-level parallelism (latency-bound otherwise)
__global__ void count_kernel(const int* __restrict__ dst) {
    int base = blockIdx.x * 1024 + threadIdx.x;
    int d0 = dst[base];
    int d1 = dst[base + 256];
    int d2 = dst[base + 512];
    int d3 = dst[base + 768];
    atomicAdd(&g_cnt[d0], 1);
    atomicAdd(&g_cnt[d1], 1);
    atomicAdd(&g_cnt[d2], 1);
    atomicAdd(&g_cnt[d3], 1);
}

__global__ void scan_kernel() {
    __shared__ int ssum[256];
    int t = threadIdx.x;
    int base = t * 32;
    int vals[32];
    int s = 0;
#pragma unroll
    for (int j = 0; j < 32; j++) { vals[j] = g_cnt[base + j]; s += vals[j]; }
    ssum[t] = s;
    __syncthreads();
#pragma unroll
    for (int off = 1; off < 256; off <<= 1) {
        int v = (t >= off) ? ssum[t - off] : 0;
        __syncthreads();
        ssum[t] += v;
        __syncthreads();
    }
    int run = ssum[t] - s;
#pragma unroll
    for (int j = 0; j < 32; j++) {
        g_rowstart[base + j] = run;
        g_cursor[base + j]   = run;
        run += vals[j];
    }
    if (t == 255) g_rowstart[NN] = run;
}

__global__ void fill_kernel(const int* __restrict__ src, const int* __restrict__ dst) {
    int base = blockIdx.x * 1024 + threadIdx.x;
#pragma unroll
    for (int k = 0; k < 4; k++) {
        int e = base + k * 256;
        int d = dst[e];
        int s = src[e];
        int pos = atomicAdd(&g_cursor[d], 1);
        g_csr[pos] = s;
    }
}

// ---------------- fp32 -> bf16 hi/lo split (vectorized float4) ----------------
__global__ void conv_split_kernel(const float* __restrict__ in,
                                  __nv_bfloat16* __restrict__ hi,
                                  __nv_bfloat16* __restrict__ lo, int n4)
{
    int i = blockIdx.x * blockDim.x + threadIdx.x;
    if (i >= n4) return;
    float4 v = ((const float4*)in)[i];
    __nv_bfloat16 h0 = __float2bfloat16(v.x);
    __nv_bfloat16 h1 = __float2bfloat16(v.y);
    __nv_bfloat16 h2 = __float2bfloat16(v.z);
    __nv_bfloat16 h3 = __float2bfloat16(v.w);
    __nv_bfloat16 l0 = __float2bfloat16(v.x - __bfloat162float(h0));
    __nv_bfloat16 l1 = __float2bfloat16(v.y - __bfloat162float(h1));
    __nv_bfloat16 l2 = __float2bfloat16(v.z - __bfloat162float(h2));
    __nv_bfloat16 l3 = __float2bfloat16(v.w - __bfloat162float(h3));
    __nv_bfloat162* hp = (__nv_bfloat162*)(hi + i * 4);
    __nv_bfloat162* lp = (__nv_bfloat162*)(lo + i * 4);
    hp[0] = __nv_bfloat162(h0, h1);
    hp[1] = __nv_bfloat162(h2, h3);
    lp[0] = __nv_bfloat162(l0, l1);
    lp[1] = __nv_bfloat162(l2, l3);
}

// ---------------- bf16 mma primitive ----------------
__device__ __forceinline__ void mma_bf16(
    float* c, const uint32_t* a, const uint32_t* b)
{
    asm volatile(
        "mma.sync.aligned.m16n8k16.row.col.f32.bf16.bf16.f32 "
        "{%0,%1,%2,%3}, {%4,%5,%6,%7}, {%8,%9}, {%0,%1,%2,%3};"
        : "+f"(c[0]), "+f"(c[1]), "+f"(c[2]), "+f"(c[3])
        : "r"(a[0]), "r"(a[1]), "r"(a[2]), "r"(a[3]), "r"(b[0]), "r"(b[1]));
}

#define LDMATRIX_X4(r0, r1, r2, r3, addr) \
    asm volatile("ldmatrix.sync.aligned.m8n8.x4.shared.b16 {%0,%1,%2,%3}, [%4];" \
        : "=r"(r0), "=r"(r1), "=r"(r2), "=r"(r3) : "r"(addr))

// ---------------- split-bf16 GEMM: C[M,Nd] = (Ahi+Alo)[M,K] @ (Bhi+Blo)[Nd,K]^T ----
// (drops lo*lo term). CTA 128x64, 8 warps of 32x32, BK=64, smem rows padded to 72.
#define G12_SMEM ((128 * 72 + 64 * 72) * 2 * 2)   // 55296 B

__global__ __launch_bounds__(256) void gemm12_kernel(
    const __nv_bfloat16* __restrict__ Ahi, const __nv_bfloat16* __restrict__ Alo,
    const __nv_bfloat16* __restrict__ Bhi, const __nv_bfloat16* __restrict__ Blo,
    float* __restrict__ C, int Nd, int K)
{
    extern __shared__ __align__(16) char sm12[];
    __nv_bfloat16* sAh = (__nv_bfloat16*)sm12;        // 128*72
    __nv_bfloat16* sAl = sAh + 128 * 72;
    __nv_bfloat16* sBh = sAl + 128 * 72;              // 64*72
    __nv_bfloat16* sBl = sBh + 64 * 72;

    int tid  = threadIdx.x;
    int lane = tid & 31;
    int w    = tid >> 5;
    int wm = (w >> 1) * 32;
    int wn = (w & 1) * 32;
    int grp = lane >> 2;
    int qid = lane & 3;
    int m0 = blockIdx.y * 128;
    int n0 = blockIdx.x * 64;

    float acc[2][4][4];
#pragma unroll
    for (int mt = 0; mt < 2; mt++)
#pragma unroll
        for (int nt = 0; nt < 4; nt++)
#pragma unroll
            for (int r = 0; r < 4; r++) acc[mt][nt][r] = 0.f;

    for (int kt = 0; kt < K; kt += 64) {
#pragma unroll
        for (int it = 0; it < 4; it++) {
            int i = it * 256 + tid;
            int row = i >> 3, u = i & 7;
            size_t go = (size_t)(m0 + row) * K + kt + u * 8;
            int so = row * 72 + u * 8;
            *(uint4*)(sAh + so) = *(const uint4*)(Ahi + go);
            *(uint4*)(sAl + so) = *(const uint4*)(Alo + go);
        }
#pragma unroll
        for (int it = 0; it < 2; it++) {
            int i = it * 256 + tid;
            int row = i >> 3, u = i & 7;
            size_t go = (size_t)(n0 + row) * K + kt + u * 8;
            int so = row * 72 + u * 8;
            *(uint4*)(sBh + so) = *(const uint4*)(Bhi + go);
            *(uint4*)(sBl + so) = *(const uint4*)(Blo + go);
        }
        __syncthreads();
#pragma unroll
        for (int ks = 0; ks < 4; ks++) {
            int k0 = ks * 16 + qid * 2;
            uint32_t ah[2][4], al[2][4], bh[4][2], bl[4][2];
#pragma unroll
            for (int mt = 0; mt < 2; mt++) {
                const __nv_bfloat16* p = sAh + (wm + mt * 16 + grp) * 72 + k0;
                ah[mt][0] = *(const uint32_t*)(p);
                ah[mt][1] = *(const uint32_t*)(p + 8 * 72);
                ah[mt][2] = *(const uint32_t*)(p + 8);
                ah[mt][3] = *(const uint32_t*)(p + 8 * 72 + 8);
                const __nv_bfloat16* q = sAl + (wm + mt * 16 + grp) * 72 + k0;
                al[mt][0] = *(const uint32_t*)(q);
                al[mt][1] = *(const uint32_t*)(q + 8 * 72);
                al[mt][2] = *(const uint32_t*)(q + 8);
                al[mt][3] = *(const uint32_t*)(q + 8 * 72 + 8);
            }
#pragma unroll
            for (int nt = 0; nt < 4; nt++) {
                const __nv_bfloat16* p = sBh + (wn + nt * 8 + grp) * 72 + k0;
                bh[nt][0] = *(const uint32_t*)(p);
                bh[nt][1] = *(const uint32_t*)(p + 8);
                const __nv_bfloat16* q = sBl + (wn + nt * 8 + grp) * 72 + k0;
                bl[nt][0] = *(const uint32_t*)(q);
                bl[nt][1] = *(const uint32_t*)(q + 8);
            }
#pragma unroll
            for (int mt = 0; mt < 2; mt++)
#pragma unroll
                for (int nt = 0; nt < 4; nt++) {
                    mma_bf16(acc[mt][nt], ah[mt], bh[nt]);
                    mma_bf16(acc[mt][nt], ah[mt], bl[nt]);
                    mma_bf16(acc[mt][nt], al[mt], bh[nt]);
                }
        }
        __syncthreads();
    }

#pragma unroll
    for (int mt = 0; mt < 2; mt++) {
        int row = m0 + wm + mt * 16 + grp;
#pragma unroll
        for (int nt = 0; nt < 4; nt++) {
            int col = n0 + wn + nt * 8 + qid * 2;
            float2 v0 = make_float2(acc[mt][nt][0], acc[mt][nt][1]);
            float2 v1 = make_float2(acc[mt][nt][2], acc[mt][nt][3]);
            *(float2*)(C + (size_t)row * Nd + col)       = v0;
            *(float2*)(C + (size_t)(row + 8) * Nd + col) = v1;
        }
    }
}

// ---------------- aggregation 1: hidden = relu(segsum + b1), emits bf16 hi/lo ----------------
__global__ __launch_bounds__(256) void agg1_relu_kernel(const float* __restrict__ b1) {
    int node = blockIdx.x * 4 + (threadIdx.x >> 6);
    int lane = threadIdx.x & 63;
    int s = g_rowstart[node];
    int e = g_rowstart[node + 1];
    float4 acc = make_float4(0.f, 0.f, 0.f, 0.f);
    int j = s;
    for (; j + 4 <= e; j += 4) {
        int i0 = g_csr[j + 0], i1 = g_csr[j + 1], i2 = g_csr[j + 2], i3 = g_csr[j + 3];
        float4 v0 = *(const float4*)(g_X1 + (size_t)i0 * HH + lane * 4);
        float4 v1 = *(const float4*)(g_X1 + (size_t)i1 * HH + lane * 4);
        float4 v2 = *(const float4*)(g_X1 + (size_t)i2 * HH + lane * 4);
        float4 v3 = *(const float4*)(g_X1 + (size_t)i3 * HH + lane * 4);
        acc.x += v0.x + v1.x + v2.x + v3.x;
        acc.y += v0.y + v1.y + v2.y + v3.y;
        acc.z += v0.z + v1.z + v2.z + v3.z;
        acc.w += v0.w + v1.w + v2.w + v3.w;
    }
    for (; j < e; j++) {
        int i0 = g_csr[j];
        float4 v0 = *(const float4*)(g_X1 + (size_t)i0 * HH + lane * 4);
        acc.x += v0.x; acc.y += v0.y; acc.z += v0.z; acc.w += v0.w;
    }
    float4 bb = ((const float4*)b1)[lane];
    float r0 = fmaxf(acc.x + bb.x, 0.f);
    float r1 = fmaxf(acc.y + bb.y, 0.f);
    float r2 = fmaxf(acc.z + bb.z, 0.f);
    float r3 = fmaxf(acc.w + bb.w, 0.f);
    // fused bf16 hi/lo split (gemm2 consumes split form only)
    __nv_bfloat16 h0 = __float2bfloat16(r0), h1 = __float2bfloat16(r1);
    __nv_bfloat16 h2 = __float2bfloat16(r2), h3 = __float2bfloat16(r3);
    __nv_bfloat16 l0 = __float2bfloat16(r0 - __bfloat162float(h0));
    __nv_bfloat16 l1 = __float2bfloat16(r1 - __bfloat162float(h1));
    __nv_bfloat16 l2 = __float2bfloat16(r2 - __bfloat162float(h2));
    __nv_bfloat16 l3 = __float2bfloat16(r3 - __bfloat162float(h3));
    __nv_bfloat162* hp = (__nv_bfloat162*)(g_hhi + (size_t)node * HH + lane * 4);
    __nv_bfloat162* lp = (__nv_bfloat162*)(g_hlo + (size_t)node * HH + lane * 4);
    hp[0] = __nv_bfloat162(h0, h1);
    hp[1] = __nv_bfloat162(h2, h3);
    lp[0] = __nv_bfloat162(l0, l1);
    lp[1] = __nv_bfloat162(l2, l3);
}

// ---------------- aggregation 2: mu/logvar + fused z split into Acat/Bcat ----------------
__global__ __launch_bounds__(256) void agg2_bias_kernel(
    const float* __restrict__ b2, const float* __restrict__ b3,
    float* __restrict__ out_mu, float* __restrict__ out_lv)
{
    int node = blockIdx.x * 8 + (threadIdx.x >> 5);
    int lane = threadIdx.x & 31;
    int s = g_rowstart[node];
    int e = g_rowstart[node + 1];
    float4 acc = make_float4(0.f, 0.f, 0.f, 0.f);
    int j = s;
    for (; j + 4 <= e; j += 4) {
        int i0 = g_csr[j + 0], i1 = g_csr[j + 1], i2 = g_csr[j + 2], i3 = g_csr[j + 3];
        float4 v0 = *(const float4*)(g_P + (size_t)i0 * P2 + lane * 4);
        float4 v1 = *(const float4*)(g_P + (size_t)i1 * P2 + lane * 4);
        float4 v2 = *(const float4*)(g_P + (size_t)i2 * P2 + lane * 4);
        float4 v3 = *(const float4*)(g_P + (size_t)i3 * P2 + lane * 4);
        acc.x += v0.x + v1.x + v2.x + v3.x;
        acc.y += v0.y + v1.y + v2.y + v3.y;
        acc.z += v0.z + v1.z + v2.z + v3.z;
        acc.w += v0.w + v1.w + v2.w + v3.w;
    }
    for (; j < e; j++) {
        int i0 = g_csr[j];
        float4 v0 = *(const float4*)(g_P + (size_t)i0 * P2 + lane * 4);
        acc.x += v0.x; acc.y += v0.y; acc.z += v0.z; acc.w += v0.w;
    }
    if (lane < 16) {
        float4 bb = ((const float4*)b2)[lane];
        acc.x += bb.x; acc.y += bb.y; acc.z += bb.z; acc.w += bb.w;
        *(float4*)(out_mu + (size_t)node * LL + lane * 4) = acc;
        // fused split of z = mu into concatenated adj-GEMM operands
        float zv[4] = {acc.x, acc.y, acc.z, acc.w};
        __nv_bfloat16* a = g_Acat + (size_t)node * 192 + lane * 4;
        __nv_bfloat16* b = g_Bcat + (size_t)node * 192 + lane * 4;
#pragma unroll
        for (int k = 0; k < 4; k++) {
            __nv_bfloat16 h = __float2bfloat16(zv[k]);
            __nv_bfloat16 l = __float2bfloat16(zv[k] - __bfloat162float(h));
            a[k] = h;  a[64 + k] = h;  a[128 + k] = l;
            b[k] = h;  b[64 + k] = l;  b[128 + k] = h;
        }
    } else {
        float4 bb = ((const float4*)b3)[lane - 16];
        acc.x += bb.x; acc.y += bb.y; acc.z += bb.z; acc.w += bb.w;
        *(float4*)(out_lv + (size_t)node * LL + (lane - 16) * 4) = acc;
    }
}

// ---------------- adj = sigmoid(Z @ Z^T) via mma.sync bf16 (split, K=192) ----------------
__device__ __forceinline__ float sigmoid_tanh(float x) {
    float t;
    asm("tanh.approx.f32 %0, %1;" : "=f"(t) : "f"(0.5f * x));
    return 0.5f * t + 0.5f;
}

// CTA 128x128, 4 warps of 64x64 each, K=192 resident. Rows padded to 200 bf16.
// Triangular 1-D grid (2080 CTAs); off-diagonal blocks mirror-write transposed.
#define G3_PAD   200
#define G3_ASZ   (128 * G3_PAD * 2)
#define G3_SMEM  (2 * G3_ASZ)

__global__ __launch_bounds__(128, 2) void gemm3_mma_kernel(float* __restrict__ adj)
{
    // decode lower-triangle block (by >= bx) from linear index
    int t = blockIdx.x;
    int by = (int)((sqrtf(8.f * (float)t + 1.f) - 1.f) * 0.5f);
    while ((by + 1) * (by + 2) / 2 <= t) by++;
    while (by * (by + 1) / 2 > t) by--;
    int bx = t - by * (by + 1) / 2;

    extern __shared__ __align__(16) char smem[];
    __nv_bfloat16* sA = (__nv_bfloat16*)smem;
    __nv_bfloat16* sB = (__nv_bfloat16*)(smem + G3_ASZ);

    int tid  = threadIdx.x;
    int lane = tid & 31;
    int w    = tid >> 5;
    int m0 = by * 128;
    int n0 = bx * 128;
    bool diag = (bx == by);

    // cooperative tile load: 2 tiles x 128 rows x 24 uint4 (192 bf16/row)
    for (int i = tid; i < 2 * 128 * 24; i += 128) {
        int tt  = (i >= 3072);
        int j   = tt ? i - 3072 : i;
        int row = j / 24;
        int u   = j % 24;
        const __nv_bfloat16* g =
            (tt ? g_Bcat + (size_t)(n0 + row) * 192
                : g_Acat + (size_t)(m0 + row) * 192) + u * 8;
        __nv_bfloat16* d = (tt ? sB : sA) + row * G3_PAD + u * 8;
        *(uint4*)d = *(const uint4*)g;
    }
    __syncthreads();

    // warp tiling: 2x2 warps, each 64 (m) x 64 (n)
    int wm = (w >> 1) * 64;
    int wn = (w & 1) * 64;
    int grp = lane >> 2;       // 0..7
    int qid = lane & 3;        // 0..3

    // ldmatrix lane-dependent base addresses
    uint32_t sA32 = (uint32_t)__cvta_generic_to_shared(sA);
    uint32_t sB32 = (uint32_t)__cvta_generic_to_shared(sB);
    int a_row = (lane & 7) + ((lane >> 3) & 1) * 8;
    int a_cb  = (lane >> 4) * 16;
    int b_row = (lane & 7) + ((lane >> 4) & 1) * 8;
    int b_cb  = ((lane >> 3) & 1) * 16;
    uint32_t a_addr[4], b_addr[4];
#pragma unroll
    for (int mt = 0; mt < 4; mt++)
        a_addr[mt] = sA32 + (uint32_t)(wm + mt * 16 + a_row) * (G3_PAD * 2) + a_cb;
#pragma unroll
    for (int np = 0; np < 4; np++)
        b_addr[np] = sB32 + (uint32_t)(wn + np * 16 + b_row) * (G3_PAD * 2) + b_cb;

    float acc[4][8][4];
#pragma unroll
    for (int mt = 0; mt < 4; mt++)
#pragma unroll
        for (int nt = 0; nt < 8; nt++)
#pragma unroll
            for (int r = 0; r < 4; r++) acc[mt][nt][r] = 0.f;

#pragma unroll
    for (int ks = 0; ks < 12; ks++) {
        uint32_t koff = ks * 32;
        uint32_t a[4][4], b[8][2];
#pragma unroll
        for (int mt = 0; mt < 4; mt++)
            LDMATRIX_X4(a[mt][0], a[mt][1], a[mt][2], a[mt][3], a_addr[mt] + koff);
#pragma unroll
        for (int np = 0; np < 4; np++)
            LDMATRIX_X4(b[2 * np][0], b[2 * np][1], b[2 * np + 1][0], b[2 * np + 1][1],
                        b_addr[np] + koff);
#pragma unroll
        for (int mt = 0; mt < 4; mt++)
#pragma unroll
            for (int nt = 0; nt < 8; nt++)
                mma_bf16(acc[mt][nt], a[mt], b[nt]);
    }

    // epilogue: sigmoid + direct stores (+ mirrored transposed stores off-diagonal)
#pragma unroll
    for (int mt = 0; mt < 4; mt++) {
        int row = m0 + wm + mt * 16 + grp;
#pragma unroll
        for (int nt = 0; nt < 8; nt++) {
            int col = n0 + wn + nt * 8 + qid * 2;
            float s0 = sigmoid_tanh(acc[mt][nt][0]);
            float s1 = sigmoid_tanh(acc[mt][nt][1]);
            float s2 = sigmoid_tanh(acc[mt][nt][2]);
            float s3 = sigmoid_tanh(acc[mt][nt][3]);
            *(float2*)(adj + (size_t)row * NN + col)       = make_float2(s0, s1);
            *(float2*)(adj + (size_t)(row + 8) * NN + col) = make_float2(s2, s3);
            if (!diag) {
                adj[(size_t)col * NN + row]           = s0;
                adj[(size_t)(col + 1) * NN + row]     = s1;
                adj[(size_t)col * NN + row + 8]       = s2;
                adj[(size_t)(col + 1) * NN + row + 8] = s3;
            }
        }
    }
}

// ---------------- launch ----------------
extern "C" void kernel_launch(void* const* d_in, const int* in_sizes, int n_in,
                              void* d_out, int out_size)
{
    const float* features = (const float*)d_in[0];
    const int*   src      = (const int*)  d_in[1];
    const int*   dst      = (const int*)  d_in[2];
    const float* W1       = (const float*)d_in[3];
    const float* b1       = (const float*)d_in[4];
    const float* W2       = (const float*)d_in[5];
    const float* b2       = (const float*)d_in[6];
    const float* W3       = (const float*)d_in[7];
    const float* b3       = (const float*)d_in[8];

    float* adj = (float*)d_out;
    float* mu  = adj + (size_t)NN * NN;
    float* lv  = mu  + (size_t)NN * LL;

    float *x1p, *pp;
    cudaGetSymbolAddress((void**)&x1p,  g_X1);
    cudaGetSymbolAddress((void**)&pp,   g_P);

    __nv_bfloat16 *fhi, *flo, *w1hi, *w1lo, *hhi, *hlo, *wchi, *wclo;
    cudaGetSymbolAddress((void**)&fhi,  g_fhi);
    cudaGetSymbolAddress((void**)&flo,  g_flo);
    cudaGetSymbolAddress((void**)&w1hi, g_w1hi);
    cudaGetSymbolAddress((void**)&w1lo, g_w1lo);
    cudaGetSymbolAddress((void**)&hhi,  g_hhi);
    cudaGetSymbolAddress((void**)&hlo,  g_hlo);
    cudaGetSymbolAddress((void**)&wchi, g_wchi);
    cudaGetSymbolAddress((void**)&wclo, g_wclo);

    cudaFuncSetAttribute(gemm3_mma_kernel,
                         cudaFuncAttributeMaxDynamicSharedMemorySize, G3_SMEM);
    cudaFuncSetAttribute(gemm12_kernel,
                         cudaFuncAttributeMaxDynamicSharedMemorySize, G12_SMEM);

    // CSR build
    zero_counts_kernel<<<NN / 256, 256>>>();
    count_kernel<<<EE / 1024, 256>>>(dst);
    scan_kernel<<<1, 256>>>();
    fill_kernel<<<EE / 1024, 256>>>(src, dst);

    // split features and weights into bf16 hi/lo
    conv_split_kernel<<<(NN * FIN / 4) / 256, 256>>>(features, fhi, flo, NN * FIN / 4);
    conv_split_kernel<<<(HH * FIN / 4) / 256, 256>>>(W1, w1hi, w1lo, HH * FIN / 4);
    conv_split_kernel<<<(LL * HH / 4) / 256, 256>>>(W2, wchi, wclo, LL * HH / 4);
    conv_split_kernel<<<(LL * HH / 4) / 256, 256>>>(W3, wchi + (size_t)LL * HH,
                                                    wclo + (size_t)LL * HH, LL * HH / 4);

    // X1 = features @ W1^T   [8192,256]  (split-bf16 tensor GEMM)
    gemm12_kernel<<<dim3(HH / 64, NN / 128), 256, G12_SMEM>>>(
        fhi, flo, w1hi, w1lo, x1p, HH, FIN);

    // hidden = relu(segsum(X1) + b1)  -> writes bf16 hi/lo directly
    agg1_relu_kernel<<<NN / 4, 256>>>(b1);

    // P = hidden @ [W2;W3]^T   [8192,128]  (split-bf16 tensor GEMM)
    gemm12_kernel<<<dim3(P2 / 64, NN / 128), 256, G12_SMEM>>>(
        hhi, hlo, wchi, wclo, pp, P2, HH);

    // mu / logvar = segsum(P) + b2/b3, with fused z-split into Acat/Bcat
    agg2_bias_kernel<<<NN / 8, 256>>>(b2, b3, mu, lv);

    // adj = sigmoid(Z @ Z^T) via mma.sync split-bf16, K=192, symmetric (triangular grid)
    gemm3_mma_kernel<<<2080, 128, G3_SMEM>>>(adj);
}

// round 7
// speedup vs baseline: 2.2218x; 1.1394x over previous
#include <cuda_runtime.h>
#include <cuda_bf16.h>
#include <cstdint>

// Problem constants (match reference)
#define NN    8192        // nodes
#define EE    262144      // edges
#define FIN   512
#define HH    256
#define LL    64
#define P2    128         // 2*L (W2 and W3 concatenated)

// ---------------- device scratch (no allocation allowed) ----------------
__device__ float g_X1[NN * HH];        // features @ W1^T          [N,256]
__device__ float g_P[NN * P2];         // hidden @ [W2;W3]^T       [N,128]
__device__ int   g_cnt[NN];
__device__ int   g_rowstart[NN + 1];
__device__ int   g_epos[EE];           // within-segment position of each edge
__device__ int   g_csr[EE];            // src indices grouped by dst

// split-bf16 operand buffers
__device__ __align__(256) __nv_bfloat16 g_fhi[NN * FIN];   // features hi
__device__ __align__(256) __nv_bfloat16 g_flo[NN * FIN];   // features lo
__device__ __align__(256) __nv_bfloat16 g_w1hi[HH * FIN];
__device__ __align__(256) __nv_bfloat16 g_w1lo[HH * FIN];
__device__ __align__(256) __nv_bfloat16 g_hhi[NN * HH];    // hidden hi
__device__ __align__(256) __nv_bfloat16 g_hlo[NN * HH];
__device__ __align__(256) __nv_bfloat16 g_wchi[P2 * HH];   // [W2;W3] hi
__device__ __align__(256) __nv_bfloat16 g_wclo[P2 * HH];

// split-bf16 concatenated operands for the adj GEMM (K = 3*64 = 192)
// A_cat[m] = [hi, hi, lo],  B_cat[n] = [hi, lo, hi]
__device__ __align__(256) __nv_bfloat16 g_Acat[NN * 192];
__device__ __align__(256) __nv_bfloat16 g_Bcat[NN * 192];

// ---------------- CSR build ----------------
__global__ void zero_counts_kernel() {
    int i = blockIdx.x * blockDim.x + threadIdx.x;
    if (i < NN) g_cnt[i] = 0;
}

// count + record within-segment position (so fill needs no atomics)
__global__ void count_kernel(const int* __restrict__ dst) {
    int base = blockIdx.x * 1024 + threadIdx.x;
#pragma unroll
    for (int k = 0; k < 4; k++) {
        int e = base + k * 256;
        int d = dst[e];
        g_epos[e] = atomicAdd(&g_cnt[d], 1);
    }
}

__global__ void scan_kernel() {
    __shared__ int ssum[256];
    int t = threadIdx.x;
    int base = t * 32;
    int vals[32];
    int s = 0;
#pragma unroll
    for (int j = 0; j < 32; j++) { vals[j] = g_cnt[base + j]; s += vals[j]; }
    ssum[t] = s;
    __syncthreads();
#pragma unroll
    for (int off = 1; off < 256; off <<= 1) {
        int v = (t >= off) ? ssum[t - off] : 0;
        __syncthreads();
        ssum[t] += v;
        __syncthreads();
    }
    int run = ssum[t] - s;
#pragma unroll
    for (int j = 0; j < 32; j++) {
        g_rowstart[base + j] = run;
        run += vals[j];
    }
    if (t == 255) g_rowstart[NN] = run;
}

// pure scatter, no atomics
__global__ void fill_kernel(const int* __restrict__ src, const int* __restrict__ dst) {
    int base = blockIdx.x * 1024 + threadIdx.x;
#pragma unroll
    for (int k = 0; k < 4; k++) {
        int e = base + k * 256;
        int d = dst[e];
        g_csr[g_rowstart[d] + g_epos[e]] = src[e];
    }
}

// ---------------- fused fp32 -> bf16 hi/lo split for all 4 operand sets ----------------
#define CVT_F   (NN * FIN / 4)                 // 1048576 float4
#define CVT_W1  (HH * FIN / 4)                 // 32768
#define CVT_W2  (LL * HH / 4)                  // 4096
#define CVT_TOT (CVT_F + CVT_W1 + 2 * CVT_W2)  // 1089536

__global__ void conv_all_kernel(const float* __restrict__ features,
                                const float* __restrict__ W1,
                                const float* __restrict__ W2,
                                const float* __restrict__ W3)
{
    int i = blockIdx.x * blockDim.x + threadIdx.x;
    if (i >= CVT_TOT) return;
    const float* in;
    __nv_bfloat16 *hi, *lo;
    int j;
    if (i < CVT_F) {
        j = i;               in = features; hi = g_fhi;  lo = g_flo;
    } else if (i < CVT_F + CVT_W1) {
        j = i - CVT_F;       in = W1;       hi = g_w1hi; lo = g_w1lo;
    } else if (i < CVT_F + CVT_W1 + CVT_W2) {
        j = i - CVT_F - CVT_W1;             in = W2;     hi = g_wchi; lo = g_wclo;
    } else {
        j = i - CVT_F - CVT_W1 - CVT_W2;    in = W3;
        hi = g_wchi + (size_t)LL * HH;      lo = g_wclo + (size_t)LL * HH;
    }
    float4 v = ((const float4*)in)[j];
    __nv_bfloat16 h0 = __float2bfloat16(v.x);
    __nv_bfloat16 h1 = __float2bfloat16(v.y);
    __nv_bfloat16 h2 = __float2bfloat16(v.z);
    __nv_bfloat16 h3 = __float2bfloat16(v.w);
    __nv_bfloat16 l0 = __float2bfloat16(v.x - __bfloat162float(h0));
    __nv_bfloat16 l1 = __float2bfloat16(v.y - __bfloat162float(h1));
    __nv_bfloat16 l2 = __float2bfloat16(v.z - __bfloat162float(h2));
    __nv_bfloat16 l3 = __float2bfloat16(v.w - __bfloat162float(h3));
    __nv_bfloat162* hp = (__nv_bfloat162*)(hi + (size_t)j * 4);
    __nv_bfloat162* lp = (__nv_bfloat162*)(lo + (size_t)j * 4);
    hp[0] = __nv_bfloat162(h0, h1);
    hp[1] = __nv_bfloat162(h2, h3);
    lp[0] = __nv_bfloat162(l0, l1);
    lp[1] = __nv_bfloat162(l2, l3);
}

// ---------------- bf16 mma primitive ----------------
__device__ __forceinline__ void mma_bf16(
    float* c, const uint32_t* a, const uint32_t* b)
{
    asm volatile(
        "mma.sync.aligned.m16n8k16.row.col.f32.bf16.bf16.f32 "
        "{%0,%1,%2,%3}, {%4,%5,%6,%7}, {%8,%9}, {%0,%1,%2,%3};"
        : "+f"(c[0]), "+f"(c[1]), "+f"(c[2]), "+f"(c[3])
        : "r"(a[0]), "r"(a[1]), "r"(a[2]), "r"(a[3]), "r"(b[0]), "r"(b[1]));
}

#define LDMATRIX_X4(r0, r1, r2, r3, addr) \
    asm volatile("ldmatrix.sync.aligned.m8n8.x4.shared.b16 {%0,%1,%2,%3}, [%4];" \
        : "=r"(r0), "=r"(r1), "=r"(r2), "=r"(r3) : "r"(addr))

// ---------------- split-bf16 GEMM: C[M,Nd] = (Ahi+Alo)[M,K] @ (Bhi+Blo)[Nd,K]^T ----
// (drops lo*lo term). CTA 128x64, 8 warps of 32x32, BK=64, smem rows padded to 72.
#define G12_SMEM ((128 * 72 + 64 * 72) * 2 * 2)   // 55296 B

__global__ __launch_bounds__(256) void gemm12_kernel(
    const __nv_bfloat16* __restrict__ Ahi, const __nv_bfloat16* __restrict__ Alo,
    const __nv_bfloat16* __restrict__ Bhi, const __nv_bfloat16* __restrict__ Blo,
    float* __restrict__ C, int Nd, int K)
{
    extern __shared__ __align__(16) char sm12[];
    __nv_bfloat16* sAh = (__nv_bfloat16*)sm12;        // 128*72
    __nv_bfloat16* sAl = sAh + 128 * 72;
    __nv_bfloat16* sBh = sAl + 128 * 72;              // 64*72
    __nv_bfloat16* sBl = sBh + 64 * 72;

    int tid  = threadIdx.x;
    int lane = tid & 31;
    int w    = tid >> 5;
    int wm = (w >> 1) * 32;
    int wn = (w & 1) * 32;
    int grp = lane >> 2;
    int qid = lane & 3;
    int m0 = blockIdx.y * 128;
    int n0 = blockIdx.x * 64;

    float acc[2][4][4];
#pragma unroll
    for (int mt = 0; mt < 2; mt++)
#pragma unroll
        for (int nt = 0; nt < 4; nt++)
#pragma unroll
            for (int r = 0; r < 4; r++) acc[mt][nt][r] = 0.f;

    for (int kt = 0; kt < K; kt += 64) {
#pragma unroll
        for (int it = 0; it < 4; it++) {
            int i = it * 256 + tid;
            int row = i >> 3, u = i & 7;
            size_t go = (size_t)(m0 + row) * K + kt + u * 8;
            int so = row * 72 + u * 8;
            *(uint4*)(sAh + so) = *(const uint4*)(Ahi + go);
            *(uint4*)(sAl + so) = *(const uint4*)(Alo + go);
        }
#pragma unroll
        for (int it = 0; it < 2; it++) {
            int i = it * 256 + tid;
            int row = i >> 3, u = i & 7;
            size_t go = (size_t)(n0 + row) * K + kt + u * 8;
            int so = row * 72 + u * 8;
            *(uint4*)(sBh + so) = *(const uint4*)(Bhi + go);
            *(uint4*)(sBl + so) = *(const uint4*)(Blo + go);
        }
        __syncthreads();
#pragma unroll
        for (int ks = 0; ks < 4; ks++) {
            int k0 = ks * 16 + qid * 2;
            uint32_t ah[2][4], al[2][4], bh[4][2], bl[4][2];
#pragma unroll
            for (int mt = 0; mt < 2; mt++) {
                const __nv_bfloat16* p = sAh + (wm + mt * 16 + grp) * 72 + k0;
                ah[mt][0] = *(const uint32_t*)(p);
                ah[mt][1] = *(const uint32_t*)(p + 8 * 72);
                ah[mt][2] = *(const uint32_t*)(p + 8);
                ah[mt][3] = *(const uint32_t*)(p + 8 * 72 + 8);
                const __nv_bfloat16* q = sAl + (wm + mt * 16 + grp) * 72 + k0;
                al[mt][0] = *(const uint32_t*)(q);
                al[mt][1] = *(const uint32_t*)(q + 8 * 72);
                al[mt][2] = *(const uint32_t*)(q + 8);
                al[mt][3] = *(const uint32_t*)(q + 8 * 72 + 8);
            }
#pragma unroll
            for (int nt = 0; nt < 4; nt++) {
                const __nv_bfloat16* p = sBh + (wn + nt * 8 + grp) * 72 + k0;
                bh[nt][0] = *(const uint32_t*)(p);
                bh[nt][1] = *(const uint32_t*)(p + 8);
                const __nv_bfloat16* q = sBl + (wn + nt * 8 + grp) * 72 + k0;
                bl[nt][0] = *(const uint32_t*)(q);
                bl[nt][1] = *(const uint32_t*)(q + 8);
            }
#pragma unroll
            for (int mt = 0; mt < 2; mt++)
#pragma unroll
                for (int nt = 0; nt < 4; nt++) {
                    mma_bf16(acc[mt][nt], ah[mt], bh[nt]);
                    mma_bf16(acc[mt][nt], ah[mt], bl[nt]);
                    mma_bf16(acc[mt][nt], al[mt], bh[nt]);
                }
        }
        __syncthreads();
    }

#pragma unroll
    for (int mt = 0; mt < 2; mt++) {
        int row = m0 + wm + mt * 16 + grp;
#pragma unroll
        for (int nt = 0; nt < 4; nt++) {
            int col = n0 + wn + nt * 8 + qid * 2;
            float2 v0 = make_float2(acc[mt][nt][0], acc[mt][nt][1]);
            float2 v1 = make_float2(acc[mt][nt][2], acc[mt][nt][3]);
            *(float2*)(C + (size_t)row * Nd + col)       = v0;
            *(float2*)(C + (size_t)(row + 8) * Nd + col) = v1;
        }
    }
}

// ---------------- aggregation 1: hidden = relu(segsum + b1), emits bf16 hi/lo ----------------
__global__ __launch_bounds__(256) void agg1_relu_kernel(const float* __restrict__ b1) {
    int node = blockIdx.x * 4 + (threadIdx.x >> 6);
    int lane = threadIdx.x & 63;
    int s = g_rowstart[node];
    int e = g_rowstart[node + 1];
    float4 acc = make_float4(0.f, 0.f, 0.f, 0.f);
    int j = s;
    for (; j + 4 <= e; j += 4) {
        int i0 = g_csr[j + 0], i1 = g_csr[j + 1], i2 = g_csr[j + 2], i3 = g_csr[j + 3];
        float4 v0 = *(const float4*)(g_X1 + (size_t)i0 * HH + lane * 4);
        float4 v1 = *(const float4*)(g_X1 + (size_t)i1 * HH + lane * 4);
        float4 v2 = *(const float4*)(g_X1 + (size_t)i2 * HH + lane * 4);
        float4 v3 = *(const float4*)(g_X1 + (size_t)i3 * HH + lane * 4);
        acc.x += v0.x + v1.x + v2.x + v3.x;
        acc.y += v0.y + v1.y + v2.y + v3.y;
        acc.z += v0.z + v1.z + v2.z + v3.z;
        acc.w += v0.w + v1.w + v2.w + v3.w;
    }
    for (; j < e; j++) {
        int i0 = g_csr[j];
        float4 v0 = *(const float4*)(g_X1 + (size_t)i0 * HH + lane * 4);
        acc.x += v0.x; acc.y += v0.y; acc.z += v0.z; acc.w += v0.w;
    }
    float4 bb = ((const float4*)b1)[lane];
    float r0 = fmaxf(acc.x + bb.x, 0.f);
    float r1 = fmaxf(acc.y + bb.y, 0.f);
    float r2 = fmaxf(acc.z + bb.z, 0.f);
    float r3 = fmaxf(acc.w + bb.w, 0.f);
    __nv_bfloat16 h0 = __float2bfloat16(r0), h1 = __float2bfloat16(r1);
    __nv_bfloat16 h2 = __float2bfloat16(r2), h3 = __float2bfloat16(r3);
    __nv_bfloat16 l0 = __float2bfloat16(r0 - __bfloat162float(h0));
    __nv_bfloat16 l1 = __float2bfloat16(r1 - __bfloat162float(h1));
    __nv_bfloat16 l2 = __float2bfloat16(r2 - __bfloat162float(h2));
    __nv_bfloat16 l3 = __float2bfloat16(r3 - __bfloat162float(h3));
    __nv_bfloat162* hp = (__nv_bfloat162*)(g_hhi + (size_t)node * HH + lane * 4);
    __nv_bfloat162* lp = (__nv_bfloat162*)(g_hlo + (size_t)node * HH + lane * 4);
    hp[0] = __nv_bfloat162(h0, h1);
    hp[1] = __nv_bfloat162(h2, h3);
    lp[0] = __nv_bfloat162(l0, l1);
    lp[1] = __nv_bfloat162(l2, l3);
}

// ---------------- aggregation 2: mu/logvar + fused z split into Acat/Bcat ----------------
__global__ __launch_bounds__(256) void agg2_bias_kernel(
    const float* __restrict__ b2, const float* __restrict__ b3,
    float* __restrict__ out_mu, float* __restrict__ out_lv)
{
    int node = blockIdx.x * 8 + (threadIdx.x >> 5);
    int lane = threadIdx.x & 31;
    int s = g_rowstart[node];
    int e = g_rowstart[node + 1];
    float4 acc = make_float4(0.f, 0.f, 0.f, 0.f);
    int j = s;
    for (; j + 4 <= e; j += 4) {
        int i0 = g_csr[j + 0], i1 = g_csr[j + 1], i2 = g_csr[j + 2], i3 = g_csr[j + 3];
        float4 v0 = *(const float4*)(g_P + (size_t)i0 * P2 + lane * 4);
        float4 v1 = *(const float4*)(g_P + (size_t)i1 * P2 + lane * 4);
        float4 v2 = *(const float4*)(g_P + (size_t)i2 * P2 + lane * 4);
        float4 v3 = *(const float4*)(g_P + (size_t)i3 * P2 + lane * 4);
        acc.x += v0.x + v1.x + v2.x + v3.x;
        acc.y += v0.y + v1.y + v2.y + v3.y;
        acc.z += v0.z + v1.z + v2.z + v3.z;
        acc.w += v0.w + v1.w + v2.w + v3.w;
    }
    for (; j < e; j++) {
        int i0 = g_csr[j];
        float4 v0 = *(const float4*)(g_P + (size_t)i0 * P2 + lane * 4);
        acc.x += v0.x; acc.y += v0.y; acc.z += v0.z; acc.w += v0.w;
    }
    if (lane < 16) {
        float4 bb = ((const float4*)b2)[lane];
        acc.x += bb.x; acc.y += bb.y; acc.z += bb.z; acc.w += bb.w;
        *(float4*)(out_mu + (size_t)node * LL + lane * 4) = acc;
        float zv[4] = {acc.x, acc.y, acc.z, acc.w};
        __nv_bfloat16* a = g_Acat + (size_t)node * 192 + lane * 4;
        __nv_bfloat16* b = g_Bcat + (size_t)node * 192 + lane * 4;
#pragma unroll
        for (int k = 0; k < 4; k++) {
            __nv_bfloat16 h = __float2bfloat16(zv[k]);
            __nv_bfloat16 l = __float2bfloat16(zv[k] - __bfloat162float(h));
            a[k] = h;  a[64 + k] = h;  a[128 + k] = l;
            b[k] = h;  b[64 + k] = l;  b[128 + k] = h;
        }
    } else {
        float4 bb = ((const float4*)b3)[lane - 16];
        acc.x += bb.x; acc.y += bb.y; acc.z += bb.z; acc.w += bb.w;
        *(float4*)(out_lv + (size_t)node * LL + (lane - 16) * 4) = acc;
    }
}

// ---------------- adj = sigmoid(Z @ Z^T) via mma.sync bf16 (split, K=192) ----------------
__device__ __forceinline__ float sigmoid_tanh(float x) {
    float t;
    asm("tanh.approx.f32 %0, %1;" : "=f"(t) : "f"(0.5f * x));
    return 0.5f * t + 0.5f;
}

// CTA 128x128, 4 warps of 64x64 each, K=192 resident. Rows padded to 200 bf16.
// Triangular 1-D grid (2080 CTAs); off-diagonal blocks mirror-write transposed.
#define G3_PAD   200
#define G3_ASZ   (128 * G3_PAD * 2)
#define G3_SMEM  (2 * G3_ASZ)

__global__ __launch_bounds__(128, 2) void gemm3_mma_kernel(float* __restrict__ adj)
{
    int t = blockIdx.x;
    int by = (int)((sqrtf(8.f * (float)t + 1.f) - 1.f) * 0.5f);
    while ((by + 1) * (by + 2) / 2 <= t) by++;
    while (by * (by + 1) / 2 > t) by--;
    int bx = t - by * (by + 1) / 2;

    extern __shared__ __align__(16) char smem[];
    __nv_bfloat16* sA = (__nv_bfloat16*)smem;
    __nv_bfloat16* sB = (__nv_bfloat16*)(smem + G3_ASZ);

    int tid  = threadIdx.x;
    int lane = tid & 31;
    int w    = tid >> 5;
    int m0 = by * 128;
    int n0 = bx * 128;
    bool diag = (bx == by);

    for (int i = tid; i < 2 * 128 * 24; i += 128) {
        int tt  = (i >= 3072);
        int j   = tt ? i - 3072 : i;
        int row = j / 24;
        int u   = j % 24;
        const __nv_bfloat16* g =
            (tt ? g_Bcat + (size_t)(n0 + row) * 192
                : g_Acat + (size_t)(m0 + row) * 192) + u * 8;
        __nv_bfloat16* d = (tt ? sB : sA) + row * G3_PAD + u * 8;
        *(uint4*)d = *(const uint4*)g;
    }
    __syncthreads();

    int wm = (w >> 1) * 64;
    int wn = (w & 1) * 64;
    int grp = lane >> 2;
    int qid = lane & 3;

    uint32_t sA32 = (uint32_t)__cvta_generic_to_shared(sA);
    uint32_t sB32 = (uint32_t)__cvta_generic_to_shared(sB);
    int a_row = (lane & 7) + ((lane >> 3) & 1) * 8;
    int a_cb  = (lane >> 4) * 16;
    int b_row = (lane & 7) + ((lane >> 4) & 1) * 8;
    int b_cb  = ((lane >> 3) & 1) * 16;
    uint32_t a_addr[4], b_addr[4];
#pragma unroll
    for (int mt = 0; mt < 4; mt++)
        a_addr[mt] = sA32 + (uint32_t)(wm + mt * 16 + a_row) * (G3_PAD * 2) + a_cb;
#pragma unroll
    for (int np = 0; np < 4; np++)
        b_addr[np] = sB32 + (uint32_t)(wn + np * 16 + b_row) * (G3_PAD * 2) + b_cb;

    float acc[4][8][4];
#pragma unroll
    for (int mt = 0; mt < 4; mt++)
#pragma unroll
        for (int nt = 0; nt < 8; nt++)
#pragma unroll
            for (int r = 0; r < 4; r++) acc[mt][nt][r] = 0.f;

#pragma unroll
    for (int ks = 0; ks < 12; ks++) {
        uint32_t koff = ks * 32;
        uint32_t a[4][4], b[8][2];
#pragma unroll
        for (int mt = 0; mt < 4; mt++)
            LDMATRIX_X4(a[mt][0], a[mt][1], a[mt][2], a[mt][3], a_addr[mt] + koff);
#pragma unroll
        for (int np = 0; np < 4; np++)
            LDMATRIX_X4(b[2 * np][0], b[2 * np][1], b[2 * np + 1][0], b[2 * np + 1][1],
                        b_addr[np] + koff);
#pragma unroll
        for (int mt = 0; mt < 4; mt++)
#pragma unroll
            for (int nt = 0; nt < 8; nt++)
                mma_bf16(acc[mt][nt], a[mt], b[nt]);
    }

#pragma unroll
    for (int mt = 0; mt < 4; mt++) {
        int row = m0 + wm + mt * 16 + grp;
#pragma unroll
        for (int nt = 0; nt < 8; nt++) {
            int col = n0 + wn + nt * 8 + qid * 2;
            float s0 = sigmoid_tanh(acc[mt][nt][0]);
            float s1 = sigmoid_tanh(acc[mt][nt][1]);
            float s2 = sigmoid_tanh(acc[mt][nt][2]);
            float s3 = sigmoid_tanh(acc[mt][nt][3]);
            *(float2*)(adj + (size_t)row * NN + col)       = make_float2(s0, s1);
            *(float2*)(adj + (size_t)(row + 8) * NN + col) = make_float2(s2, s3);
            if (!diag) {
                adj[(size_t)col * NN + row]           = s0;
                adj[(size_t)(col + 1) * NN + row]     = s1;
                adj[(size_t)col * NN + row + 8]       = s2;
                adj[(size_t)(col + 1) * NN + row + 8] = s3;
            }
        }
    }
}

// ---------------- launch ----------------
extern "C" void kernel_launch(void* const* d_in, const int* in_sizes, int n_in,
                              void* d_out, int out_size)
{
    const float* features = (const float*)d_in[0];
    const int*   src      = (const int*)  d_in[1];
    const int*   dst      = (const int*)  d_in[2];
    const float* W1       = (const float*)d_in[3];
    const float* b1       = (const float*)d_in[4];
    const float* W2       = (const float*)d_in[5];
    const float* b2       = (const float*)d_in[6];
    const float* W3       = (const float*)d_in[7];
    const float* b3       = (const float*)d_in[8];

    float* adj = (float*)d_out;
    float* mu  = adj + (size_t)NN * NN;
    float* lv  = mu  + (size_t)NN * LL;

    float *x1p, *pp;
    cudaGetSymbolAddress((void**)&x1p,  g_X1);
    cudaGetSymbolAddress((void**)&pp,   g_P);

    __nv_bfloat16 *fhi, *flo, *w1hi, *w1lo, *hhi, *hlo, *wchi, *wclo;
    cudaGetSymbolAddress((void**)&fhi,  g_fhi);
    cudaGetSymbolAddress((void**)&flo,  g_flo);
    cudaGetSymbolAddress((void**)&w1hi, g_w1hi);
    cudaGetSymbolAddress((void**)&w1lo, g_w1lo);
    cudaGetSymbolAddress((void**)&hhi,  g_hhi);
    cudaGetSymbolAddress((void**)&hlo,  g_hlo);
    cudaGetSymbolAddress((void**)&wchi, g_wchi);
    cudaGetSymbolAddress((void**)&wclo, g_wclo);

    cudaFuncSetAttribute(gemm3_mma_kernel,
                         cudaFuncAttributeMaxDynamicSharedMemorySize, G3_SMEM);
    cudaFuncSetAttribute(gemm12_kernel,
                         cudaFuncAttributeMaxDynamicSharedMemorySize, G12_SMEM);

    // side stream + fork/join events (infra, created once; no device memory)
    static cudaStream_t s2 = nullptr;
    static cudaEvent_t ev_fork = nullptr, ev_join = nullptr;
    if (s2 == nullptr) {
        cudaStreamCreateWithFlags(&s2, cudaStreamNonBlocking);
        cudaEventCreateWithFlags(&ev_fork, cudaEventDisableTiming);
        cudaEventCreateWithFlags(&ev_join, cudaEventDisableTiming);
    }

    // ---- fork: CSR chain on side stream, conv+gemm1 on main stream ----
    cudaEventRecord(ev_fork, 0);
    cudaStreamWaitEvent(s2, ev_fork, 0);

    zero_counts_kernel<<<NN / 256, 256, 0, s2>>>();
    count_kernel<<<EE / 1024, 256, 0, s2>>>(dst);
    scan_kernel<<<1, 256, 0, s2>>>();
    fill_kernel<<<EE / 1024, 256, 0, s2>>>(src, dst);
    cudaEventRecord(ev_join, s2);

    // main stream: all fp32->bf16 splits in one kernel, then gemm1
    conv_all_kernel<<<(CVT_TOT + 255) / 256, 256>>>(features, W1, W2, W3);
    gemm12_kernel<<<dim3(HH / 64, NN / 128), 256, G12_SMEM>>>(
        fhi, flo, w1hi, w1lo, x1p, HH, FIN);

    // ---- join ----
    cudaStreamWaitEvent(0, ev_join, 0);

    // hidden = relu(segsum(X1) + b1)  -> writes bf16 hi/lo directly
    agg1_relu_kernel<<<NN / 4, 256>>>(b1);

    // P = hidden @ [W2;W3]^T   [8192,128]
    gemm12_kernel<<<dim3(P2 / 64, NN / 128), 256, G12_SMEM>>>(
        hhi, hlo, wchi, wclo, pp, P2, HH);

    // mu / logvar = segsum(P) + b2/b3, with fused z-split into Acat/Bcat
    agg2_bias_kernel<<<NN / 8, 256>>>(b2, b3, mu, lv);

    // adj = sigmoid(Z @ Z^T) via mma.sync split-bf16, K=192, symmetric
    gemm3_mma_kernel<<<2080, 128, G3_SMEM>>>(adj);
}

// round 8
// speedup vs baseline: 2.2554x; 1.0151x over previous
#include <cuda_runtime.h>
#include <cuda_bf16.h>
#include <cstdint>

// Problem constants (match reference)
#define NN    8192        // nodes
#define EE    262144      // edges
#define FIN   512
#define HH    256
#define LL    64
#define P2    128         // 2*L (W2 and W3 concatenated)

// ---------------- device scratch (no allocation allowed) ----------------
__device__ float g_X1[NN * HH];        // features @ W1^T          [N,256]
__device__ float g_hidden[NN * HH];    // relu(agg1 + b1)          [N,256]
__device__ float g_P[NN * P2];         // hidden @ [W2;W3]^T       [N,128]
__device__ int   g_cnt[NN];
__device__ int   g_rowstart[NN + 1];
__device__ int   g_epos[EE];           // within-segment position of each edge
__device__ int   g_csr[EE];            // src indices grouped by dst

// split-bf16 weight buffers (weights only; activations split inline in GEMMs)
__device__ __align__(256) __nv_bfloat16 g_w1hi[HH * FIN];
__device__ __align__(256) __nv_bfloat16 g_w1lo[HH * FIN];
__device__ __align__(256) __nv_bfloat16 g_wchi[P2 * HH];   // [W2;W3] hi
__device__ __align__(256) __nv_bfloat16 g_wclo[P2 * HH];

// split-bf16 concatenated operands for the adj GEMM (K = 3*64 = 192)
// A_cat[m] = [hi, hi, lo],  B_cat[n] = [hi, lo, hi]
__device__ __align__(256) __nv_bfloat16 g_Acat[NN * 192];
__device__ __align__(256) __nv_bfloat16 g_Bcat[NN * 192];

// ---------------- CSR build ----------------
__global__ void zero_counts_kernel() {
    int i = blockIdx.x * blockDim.x + threadIdx.x;
    if (i < NN) g_cnt[i] = 0;
}

// count + record within-segment position (so fill needs no atomics)
__global__ void count_kernel(const int* __restrict__ dst) {
    int base = blockIdx.x * 1024 + threadIdx.x;
#pragma unroll
    for (int k = 0; k < 4; k++) {
        int e = base + k * 256;
        int d = dst[e];
        g_epos[e] = atomicAdd(&g_cnt[d], 1);
    }
}

__global__ void scan_kernel() {
    __shared__ int ssum[256];
    int t = threadIdx.x;
    int base = t * 32;
    int vals[32];
    int s = 0;
#pragma unroll
    for (int j = 0; j < 32; j++) { vals[j] = g_cnt[base + j]; s += vals[j]; }
    ssum[t] = s;
    __syncthreads();
#pragma unroll
    for (int off = 1; off < 256; off <<= 1) {
        int v = (t >= off) ? ssum[t - off] : 0;
        __syncthreads();
        ssum[t] += v;
        __syncthreads();
    }
    int run = ssum[t] - s;
#pragma unroll
    for (int j = 0; j < 32; j++) {
        g_rowstart[base + j] = run;
        run += vals[j];
    }
    if (t == 255) g_rowstart[NN] = run;
}

// pure scatter, no atomics
__global__ void fill_kernel(const int* __restrict__ src, const int* __restrict__ dst) {
    int base = blockIdx.x * 1024 + threadIdx.x;
#pragma unroll
    for (int k = 0; k < 4; k++) {
        int e = base + k * 256;
        int d = dst[e];
        g_csr[g_rowstart[d] + g_epos[e]] = src[e];
    }
}

// ---------------- weight fp32 -> bf16 hi/lo split (small, W1/W2/W3 only) ----------------
#define CVT_W1  (HH * FIN / 4)                 // 32768 float4
#define CVT_W2  (LL * HH / 4)                  // 4096
#define CVT_WTOT (CVT_W1 + 2 * CVT_W2)         // 40960

__global__ void conv_w_kernel(const float* __restrict__ W1,
                              const float* __restrict__ W2,
                              const float* __restrict__ W3)
{
    int i = blockIdx.x * blockDim.x + threadIdx.x;
    if (i >= CVT_WTOT) return;
    const float* in;
    __nv_bfloat16 *hi, *lo;
    int j;
    if (i < CVT_W1) {
        j = i;               in = W1;  hi = g_w1hi; lo = g_w1lo;
    } else if (i < CVT_W1 + CVT_W2) {
        j = i - CVT_W1;      in = W2;  hi = g_wchi; lo = g_wclo;
    } else {
        j = i - CVT_W1 - CVT_W2;       in = W3;
        hi = g_wchi + (size_t)LL * HH; lo = g_wclo + (size_t)LL * HH;
    }
    float4 v = ((const float4*)in)[j];
    __nv_bfloat16 h0 = __float2bfloat16(v.x);
    __nv_bfloat16 h1 = __float2bfloat16(v.y);
    __nv_bfloat16 h2 = __float2bfloat16(v.z);
    __nv_bfloat16 h3 = __float2bfloat16(v.w);
    __nv_bfloat16 l0 = __float2bfloat16(v.x - __bfloat162float(h0));
    __nv_bfloat16 l1 = __float2bfloat16(v.y - __bfloat162float(h1));
    __nv_bfloat16 l2 = __float2bfloat16(v.z - __bfloat162float(h2));
    __nv_bfloat16 l3 = __float2bfloat16(v.w - __bfloat162float(h3));
    __nv_bfloat162* hp = (__nv_bfloat162*)(hi + (size_t)j * 4);
    __nv_bfloat162* lp = (__nv_bfloat162*)(lo + (size_t)j * 4);
    hp[0] = __nv_bfloat162(h0, h1);
    hp[1] = __nv_bfloat162(h2, h3);
    lp[0] = __nv_bfloat162(l0, l1);
    lp[1] = __nv_bfloat162(l2, l3);
}

// ---------------- bf16 mma primitive ----------------
__device__ __forceinline__ void mma_bf16(
    float* c, const uint32_t* a, const uint32_t* b)
{
    asm volatile(
        "mma.sync.aligned.m16n8k16.row.col.f32.bf16.bf16.f32 "
        "{%0,%1,%2,%3}, {%4,%5,%6,%7}, {%8,%9}, {%0,%1,%2,%3};"
        : "+f"(c[0]), "+f"(c[1]), "+f"(c[2]), "+f"(c[3])
        : "r"(a[0]), "r"(a[1]), "r"(a[2]), "r"(a[3]), "r"(b[0]), "r"(b[1]));
}

#define LDMATRIX_X4(r0, r1, r2, r3, addr) \
    asm volatile("ldmatrix.sync.aligned.m8n8.x4.shared.b16 {%0,%1,%2,%3}, [%4];" \
        : "=r"(r0), "=r"(r1), "=r"(r2), "=r"(r3) : "r"(addr))

// ---------------- split-bf16 GEMM with inline A split ----------------
// C[M,Nd] = A[M,K](fp32, split inline) @ (Bhi+Blo)[Nd,K]^T, drops lo*lo term.
// CTA 128x64, 8 warps of 32x32, BK=64, smem rows padded to 72 bf16 (144B: bank
// stride 4 words -> ldmatrix conflict-free).
#define G12_SMEM ((128 * 72 + 64 * 72) * 2 * 2)   // 55296 B

__global__ __launch_bounds__(256) void gemm12_kernel(
    const float* __restrict__ A,
    const __nv_bfloat16* __restrict__ Bhi, const __nv_bfloat16* __restrict__ Blo,
    float* __restrict__ C, int Nd, int K)
{
    extern __shared__ __align__(16) char sm12[];
    __nv_bfloat16* sAh = (__nv_bfloat16*)sm12;        // 128*72
    __nv_bfloat16* sAl = sAh + 128 * 72;
    __nv_bfloat16* sBh = sAl + 128 * 72;              // 64*72
    __nv_bfloat16* sBl = sBh + 64 * 72;

    int tid  = threadIdx.x;
    int lane = tid & 31;
    int w    = tid >> 5;
    int wm = (w >> 1) * 32;
    int wn = (w & 1) * 32;
    int grp = lane >> 2;
    int qid = lane & 3;
    int m0 = blockIdx.y * 128;
    int n0 = blockIdx.x * 64;

    // ldmatrix lane addressing (same pattern as gemm3)
    uint32_t sAh32 = (uint32_t)__cvta_generic_to_shared(sAh);
    uint32_t sAl32 = (uint32_t)__cvta_generic_to_shared(sAl);
    uint32_t sBh32 = (uint32_t)__cvta_generic_to_shared(sBh);
    uint32_t sBl32 = (uint32_t)__cvta_generic_to_shared(sBl);
    int a_row = (lane & 7) + ((lane >> 3) & 1) * 8;
    int a_cb  = (lane >> 4) * 16;
    int b_row = (lane & 7) + ((lane >> 4) & 1) * 8;
    int b_cb  = ((lane >> 3) & 1) * 16;
    uint32_t aH[2], aL[2], bH[2], bL[2];
#pragma unroll
    for (int mt = 0; mt < 2; mt++) {
        uint32_t off = (uint32_t)(wm + mt * 16 + a_row) * 144 + a_cb;
        aH[mt] = sAh32 + off;  aL[mt] = sAl32 + off;
    }
#pragma unroll
    for (int np = 0; np < 2; np++) {
        uint32_t off = (uint32_t)(wn + np * 16 + b_row) * 144 + b_cb;
        bH[np] = sBh32 + off;  bL[np] = sBl32 + off;
    }

    float acc[2][4][4];
#pragma unroll
    for (int mt = 0; mt < 2; mt++)
#pragma unroll
        for (int nt = 0; nt < 4; nt++)
#pragma unroll
            for (int r = 0; r < 4; r++) acc[mt][nt][r] = 0.f;

    for (int kt = 0; kt < K; kt += 64) {
        // A: 128 rows x 64 cols fp32, split inline to bf16 hi/lo
#pragma unroll
        for (int it = 0; it < 8; it++) {
            int i = it * 256 + tid;
            int row = i >> 4, u = i & 15;           // 16 float4 per row
            float4 v = *(const float4*)(A + (size_t)(m0 + row) * K + kt + u * 4);
            __nv_bfloat16 h0 = __float2bfloat16(v.x);
            __nv_bfloat16 h1 = __float2bfloat16(v.y);
            __nv_bfloat16 h2 = __float2bfloat16(v.z);
            __nv_bfloat16 h3 = __float2bfloat16(v.w);
            __nv_bfloat16 l0 = __float2bfloat16(v.x - __bfloat162float(h0));
            __nv_bfloat16 l1 = __float2bfloat16(v.y - __bfloat162float(h1));
            __nv_bfloat16 l2 = __float2bfloat16(v.z - __bfloat162float(h2));
            __nv_bfloat16 l3 = __float2bfloat16(v.w - __bfloat162float(h3));
            int so = row * 72 + u * 4;
            __nv_bfloat162 hh0(h0, h1), hh1(h2, h3), ll0(l0, l1), ll1(l2, l3);
            uint2 hv, lv;
            hv.x = *(uint32_t*)&hh0;  hv.y = *(uint32_t*)&hh1;
            lv.x = *(uint32_t*)&ll0;  lv.y = *(uint32_t*)&ll1;
            *(uint2*)(sAh + so) = hv;
            *(uint2*)(sAl + so) = lv;
        }
        // B: presplit bf16
#pragma unroll
        for (int it = 0; it < 2; it++) {
            int i = it * 256 + tid;
            int row = i >> 3, u = i & 7;
            size_t go = (size_t)(n0 + row) * K + kt + u * 8;
            int so = row * 72 + u * 8;
            *(uint4*)(sBh + so) = *(const uint4*)(Bhi + go);
            *(uint4*)(sBl + so) = *(const uint4*)(Blo + go);
        }
        __syncthreads();
#pragma unroll
        for (int ks = 0; ks < 4; ks++) {
            uint32_t koff = ks * 32;                 // 16 bf16 = 32 bytes
            uint32_t ah[2][4], al[2][4], bh[4][2], bl[4][2];
#pragma unroll
            for (int mt = 0; mt < 2; mt++) {
                LDMATRIX_X4(ah[mt][0], ah[mt][1], ah[mt][2], ah[mt][3], aH[mt] + koff);
                LDMATRIX_X4(al[mt][0], al[mt][1], al[mt][2], al[mt][3], aL[mt] + koff);
            }
#pragma unroll
            for (int np = 0; np < 2; np++) {
                LDMATRIX_X4(bh[2*np][0], bh[2*np][1], bh[2*np+1][0], bh[2*np+1][1],
                            bH[np] + koff);
                LDMATRIX_X4(bl[2*np][0], bl[2*np][1], bl[2*np+1][0], bl[2*np+1][1],
                            bL[np] + koff);
            }
#pragma unroll
            for (int mt = 0; mt < 2; mt++)
#pragma unroll
                for (int nt = 0; nt < 4; nt++) {
                    mma_bf16(acc[mt][nt], ah[mt], bh[nt]);
                    mma_bf16(acc[mt][nt], ah[mt], bl[nt]);
                    mma_bf16(acc[mt][nt], al[mt], bh[nt]);
                }
        }
        __syncthreads();
    }

#pragma unroll
    for (int mt = 0; mt < 2; mt++) {
        int row = m0 + wm + mt * 16 + grp;
#pragma unroll
        for (int nt = 0; nt < 4; nt++) {
            int col = n0 + wn + nt * 8 + qid * 2;
            float2 v0 = make_float2(acc[mt][nt][0], acc[mt][nt][1]);
            float2 v1 = make_float2(acc[mt][nt][2], acc[mt][nt][3]);
            *(float2*)(C + (size_t)row * Nd + col)       = v0;
            *(float2*)(C + (size_t)(row + 8) * Nd + col) = v1;
        }
    }
}

// ---------------- aggregation 1: hidden = relu(segsum + b1), fp32 out ----------------
__global__ __launch_bounds__(256) void agg1_relu_kernel(const float* __restrict__ b1) {
    int node = blockIdx.x * 4 + (threadIdx.x >> 6);
    int lane = threadIdx.x & 63;
    int s = g_rowstart[node];
    int e = g_rowstart[node + 1];
    float4 acc = make_float4(0.f, 0.f, 0.f, 0.f);
    int j = s;
    for (; j + 4 <= e; j += 4) {
        int i0 = g_csr[j + 0], i1 = g_csr[j + 1], i2 = g_csr[j + 2], i3 = g_csr[j + 3];
        float4 v0 = *(const float4*)(g_X1 + (size_t)i0 * HH + lane * 4);
        float4 v1 = *(const float4*)(g_X1 + (size_t)i1 * HH + lane * 4);
        float4 v2 = *(const float4*)(g_X1 + (size_t)i2 * HH + lane * 4);
        float4 v3 = *(const float4*)(g_X1 + (size_t)i3 * HH + lane * 4);
        acc.x += v0.x + v1.x + v2.x + v3.x;
        acc.y += v0.y + v1.y + v2.y + v3.y;
        acc.z += v0.z + v1.z + v2.z + v3.z;
        acc.w += v0.w + v1.w + v2.w + v3.w;
    }
    for (; j < e; j++) {
        int i0 = g_csr[j];
        float4 v0 = *(const float4*)(g_X1 + (size_t)i0 * HH + lane * 4);
        acc.x += v0.x; acc.y += v0.y; acc.z += v0.z; acc.w += v0.w;
    }
    float4 bb = ((const float4*)b1)[lane];
    float4 r;
    r.x = fmaxf(acc.x + bb.x, 0.f);
    r.y = fmaxf(acc.y + bb.y, 0.f);
    r.z = fmaxf(acc.z + bb.z, 0.f);
    r.w = fmaxf(acc.w + bb.w, 0.f);
    *(float4*)(g_hidden + (size_t)node * HH + lane * 4) = r;
}

// ---------------- aggregation 2: mu/logvar + fused z split into Acat/Bcat ----------------
__global__ __launch_bounds__(256) void agg2_bias_kernel(
    const float* __restrict__ b2, const float* __restrict__ b3,
    float* __restrict__ out_mu, float* __restrict__ out_lv)
{
    int node = blockIdx.x * 8 + (threadIdx.x >> 5);
    int lane = threadIdx.x & 31;
    int s = g_rowstart[node];
    int e = g_rowstart[node + 1];
    float4 acc = make_float4(0.f, 0.f, 0.f, 0.f);
    int j = s;
    for (; j + 4 <= e; j += 4) {
        int i0 = g_csr[j + 0], i1 = g_csr[j + 1], i2 = g_csr[j + 2], i3 = g_csr[j + 3];
        float4 v0 = *(const float4*)(g_P + (size_t)i0 * P2 + lane * 4);
        float4 v1 = *(const float4*)(g_P + (size_t)i1 * P2 + lane * 4);
        float4 v2 = *(const float4*)(g_P + (size_t)i2 * P2 + lane * 4);
        float4 v3 = *(const float4*)(g_P + (size_t)i3 * P2 + lane * 4);
        acc.x += v0.x + v1.x + v2.x + v3.x;
        acc.y += v0.y + v1.y + v2.y + v3.y;
        acc.z += v0.z + v1.z + v2.z + v3.z;
        acc.w += v0.w + v1.w + v2.w + v3.w;
    }
    for (; j < e; j++) {
        int i0 = g_csr[j];
        float4 v0 = *(const float4*)(g_P + (size_t)i0 * P2 + lane * 4);
        acc.x += v0.x; acc.y += v0.y; acc.z += v0.z; acc.w += v0.w;
    }
    if (lane < 16) {
        float4 bb = ((const float4*)b2)[lane];
        acc.x += bb.x; acc.y += bb.y; acc.z += bb.z; acc.w += bb.w;
        *(float4*)(out_mu + (size_t)node * LL + lane * 4) = acc;
        float zv[4] = {acc.x, acc.y, acc.z, acc.w};
        __nv_bfloat16* a = g_Acat + (size_t)node * 192 + lane * 4;
        __nv_bfloat16* b = g_Bcat + (size_t)node * 192 + lane * 4;
#pragma unroll
        for (int k = 0; k < 4; k++) {
            __nv_bfloat16 h = __float2bfloat16(zv[k]);
            __nv_bfloat16 l = __float2bfloat16(zv[k] - __bfloat162float(h));
            a[k] = h;  a[64 + k] = h;  a[128 + k] = l;
            b[k] = h;  b[64 + k] = l;  b[128 + k] = h;
        }
    } else {
        float4 bb = ((const float4*)b3)[lane - 16];
        acc.x += bb.x; acc.y += bb.y; acc.z += bb.z; acc.w += bb.w;
        *(float4*)(out_lv + (size_t)node * LL + (lane - 16) * 4) = acc;
    }
}

// ---------------- adj = sigmoid(Z @ Z^T) via mma.sync bf16 (split, K=192) ----------------
__device__ __forceinline__ float sigmoid_tanh(float x) {
    float t;
    asm("tanh.approx.f32 %0, %1;" : "=f"(t) : "f"(0.5f * x));
    return 0.5f * t + 0.5f;
}

// CTA 128x128, 4 warps of 64x64 each, K=192 resident. Rows padded to 200 bf16.
// Triangular 1-D grid (2080 CTAs); off-diagonal blocks mirror-write transposed.
#define G3_PAD   200
#define G3_ASZ   (128 * G3_PAD * 2)
#define G3_SMEM  (2 * G3_ASZ)

__global__ __launch_bounds__(128, 2) void gemm3_mma_kernel(float* __restrict__ adj)
{
    int t = blockIdx.x;
    int by = (int)((sqrtf(8.f * (float)t + 1.f) - 1.f) * 0.5f);
    while ((by + 1) * (by + 2) / 2 <= t) by++;
    while (by * (by + 1) / 2 > t) by--;
    int bx = t - by * (by + 1) / 2;

    extern __shared__ __align__(16) char smem[];
    __nv_bfloat16* sA = (__nv_bfloat16*)smem;
    __nv_bfloat16* sB = (__nv_bfloat16*)(smem + G3_ASZ);

    int tid  = threadIdx.x;
    int lane = tid & 31;
    int w    = tid >> 5;
    int m0 = by * 128;
    int n0 = bx * 128;
    bool diag = (bx == by);

    for (int i = tid; i < 2 * 128 * 24; i += 128) {
        int tt  = (i >= 3072);
        int j   = tt ? i - 3072 : i;
        int row = j / 24;
        int u   = j % 24;
        const __nv_bfloat16* g =
            (tt ? g_Bcat + (size_t)(n0 + row) * 192
                : g_Acat + (size_t)(m0 + row) * 192) + u * 8;
        __nv_bfloat16* d = (tt ? sB : sA) + row * G3_PAD + u * 8;
        *(uint4*)d = *(const uint4*)g;
    }
    __syncthreads();

    int wm = (w >> 1) * 64;
    int wn = (w & 1) * 64;
    int grp = lane >> 2;
    int qid = lane & 3;

    uint32_t sA32 = (uint32_t)__cvta_generic_to_shared(sA);
    uint32_t sB32 = (uint32_t)__cvta_generic_to_shared(sB);
    int a_row = (lane & 7) + ((lane >> 3) & 1) * 8;
    int a_cb  = (lane >> 4) * 16;
    int b_row = (lane & 7) + ((lane >> 4) & 1) * 8;
    int b_cb  = ((lane >> 3) & 1) * 16;
    uint32_t a_addr[4], b_addr[4];
#pragma unroll
    for (int mt = 0; mt < 4; mt++)
        a_addr[mt] = sA32 + (uint32_t)(wm + mt * 16 + a_row) * (G3_PAD * 2) + a_cb;
#pragma unroll
    for (int np = 0; np < 4; np++)
        b_addr[np] = sB32 + (uint32_t)(wn + np * 16 + b_row) * (G3_PAD * 2) + b_cb;

    float acc[4][8][4];
#pragma unroll
    for (int mt = 0; mt < 4; mt++)
#pragma unroll
        for (int nt = 0; nt < 8; nt++)
#pragma unroll
            for (int r = 0; r < 4; r++) acc[mt][nt][r] = 0.f;

#pragma unroll
    for (int ks = 0; ks < 12; ks++) {
        uint32_t koff = ks * 32;
        uint32_t a[4][4], b[8][2];
#pragma unroll
        for (int mt = 0; mt < 4; mt++)
            LDMATRIX_X4(a[mt][0], a[mt][1], a[mt][2], a[mt][3], a_addr[mt] + koff);
#pragma unroll
        for (int np = 0; np < 4; np++)
            LDMATRIX_X4(b[2 * np][0], b[2 * np][1], b[2 * np + 1][0], b[2 * np + 1][1],
                        b_addr[np] + koff);
#pragma unroll
        for (int mt = 0; mt < 4; mt++)
#pragma unroll
            for (int nt = 0; nt < 8; nt++)
                mma_bf16(acc[mt][nt], a[mt], b[nt]);
    }

#pragma unroll
    for (int mt = 0; mt < 4; mt++) {
        int row = m0 + wm + mt * 16 + grp;
#pragma unroll
        for (int nt = 0; nt < 8; nt++) {
            int col = n0 + wn + nt * 8 + qid * 2;
            float s0 = sigmoid_tanh(acc[mt][nt][0]);
            float s1 = sigmoid_tanh(acc[mt][nt][1]);
            float s2 = sigmoid_tanh(acc[mt][nt][2]);
            float s3 = sigmoid_tanh(acc[mt][nt][3]);
            *(float2*)(adj + (size_t)row * NN + col)       = make_float2(s0, s1);
            *(float2*)(adj + (size_t)(row + 8) * NN + col) = make_float2(s2, s3);
            if (!diag) {
                adj[(size_t)col * NN + row]           = s0;
                adj[(size_t)(col + 1) * NN + row]     = s1;
                adj[(size_t)col * NN + row + 8]       = s2;
                adj[(size_t)(col + 1) * NN + row + 8] = s3;
            }
        }
    }
}

// ---------------- launch ----------------
extern "C" void kernel_launch(void* const* d_in, const int* in_sizes, int n_in,
                              void* d_out, int out_size)
{
    const float* features = (const float*)d_in[0];
    const int*   src      = (const int*)  d_in[1];
    const int*   dst      = (const int*)  d_in[2];
    const float* W1       = (const float*)d_in[3];
    const float* b1       = (const float*)d_in[4];
    const float* W2       = (const float*)d_in[5];
    const float* b2       = (const float*)d_in[6];
    const float* W3       = (const float*)d_in[7];
    const float* b3       = (const float*)d_in[8];

    float* adj = (float*)d_out;
    float* mu  = adj + (size_t)NN * NN;
    float* lv  = mu  + (size_t)NN * LL;

    float *x1p, *hidp, *pp;
    cudaGetSymbolAddress((void**)&x1p,  g_X1);
    cudaGetSymbolAddress((void**)&hidp, g_hidden);
    cudaGetSymbolAddress((void**)&pp,   g_P);

    __nv_bfloat16 *w1hi, *w1lo, *wchi, *wclo;
    cudaGetSymbolAddress((void**)&w1hi, g_w1hi);
    cudaGetSymbolAddress((void**)&w1lo, g_w1lo);
    cudaGetSymbolAddress((void**)&wchi, g_wchi);
    cudaGetSymbolAddress((void**)&wclo, g_wclo);

    cudaFuncSetAttribute(gemm3_mma_kernel,
                         cudaFuncAttributeMaxDynamicSharedMemorySize, G3_SMEM);
    cudaFuncSetAttribute(gemm12_kernel,
                         cudaFuncAttributeMaxDynamicSharedMemorySize, G12_SMEM);

    // side stream + fork/join events (infra, created once; no device memory)
    static cudaStream_t s2 = nullptr;
    static cudaEvent_t ev_fork = nullptr, ev_join = nullptr;
    if (s2 == nullptr) {
        cudaStreamCreateWithFlags(&s2, cudaStreamNonBlocking);
        cudaEventCreateWithFlags(&ev_fork, cudaEventDisableTiming);
        cudaEventCreateWithFlags(&ev_join, cudaEventDisableTiming);
    }

    // ---- fork: CSR chain on side stream, conv+gemm1 on main stream ----
    cudaEventRecord(ev_fork, 0);
    cudaStreamWaitEvent(s2, ev_fork, 0);

    zero_counts_kernel<<<NN / 256, 256, 0, s2>>>();
    count_kernel<<<EE / 1024, 256, 0, s2>>>(dst);
    scan_kernel<<<1, 256, 0, s2>>>();
    fill_kernel<<<EE / 1024, 256, 0, s2>>>(src, dst);
    cudaEventRecord(ev_join, s2);

    // main stream: tiny weight splits, then gemm1 (features split inline)
    conv_w_kernel<<<(CVT_WTOT + 255) / 256, 256>>>(W1, W2, W3);
    gemm12_kernel<<<dim3(HH / 64, NN / 128), 256, G12_SMEM>>>(
        features, w1hi, w1lo, x1p, HH, FIN);

    // ---- join ----
    cudaStreamWaitEvent(0, ev_join, 0);

    // hidden = relu(segsum(X1) + b1)  (fp32)
    agg1_relu_kernel<<<NN / 4, 256>>>(b1);

    // P = hidden @ [W2;W3]^T   [8192,128]  (hidden split inline)
    gemm12_kernel<<<dim3(P2 / 64, NN / 128), 256, G12_SMEM>>>(
        hidp, wchi, wclo, pp, P2, HH);

    // mu / logvar = segsum(P) + b2/b3, with fused z-split into Acat/Bcat
    agg2_bias_kernel<<<NN / 8, 256>>>(b2, b3, mu, lv);

    // adj = sigmoid(Z @ Z^T) via mma.sync split-bf16, K=192, symmetric
    gemm3_mma_kernel<<<2080, 128, G3_SMEM>>>(adj);
}

// round 9
// speedup vs baseline: 2.2783x; 1.0102x over previous
#include <cuda_runtime.h>
#include <cuda_bf16.h>
#include <cstdint>

// Problem constants (match reference)
#define NN    8192        // nodes
#define EE    262144      // edges
#define FIN   512
#define HH    256
#define LL    64
#define P2    128         // 2*L (W2 and W3 concatenated)

// ---------------- device scratch (no allocation allowed) ----------------
__device__ float g_X1[NN * HH];        // features @ W1^T          [N,256]
__device__ float g_hidden[NN * HH];    // relu(agg1 + b1)          [N,256]
__device__ float g_P[NN * P2];         // hidden @ [W2;W3]^T       [N,128]
__device__ int   g_cnt[NN];
__device__ int   g_rowstart[NN + 1];
__device__ int   g_epos[EE];           // within-segment position of each edge
__device__ int   g_csr[EE];            // src indices grouped by dst

// split-bf16 weight buffers (weights only; activations split inline in GEMMs)
__device__ __align__(256) __nv_bfloat16 g_w1hi[HH * FIN];
__device__ __align__(256) __nv_bfloat16 g_w1lo[HH * FIN];
__device__ __align__(256) __nv_bfloat16 g_wchi[P2 * HH];   // [W2;W3] hi
__device__ __align__(256) __nv_bfloat16 g_wclo[P2 * HH];

// split-bf16 concatenated operands for the adj GEMM (K = 3*64 = 192)
// A_cat[m] = [hi, hi, lo],  B_cat[n] = [hi, lo, hi]
__device__ __align__(256) __nv_bfloat16 g_Acat[NN * 192];
__device__ __align__(256) __nv_bfloat16 g_Bcat[NN * 192];

// ---------------- CSR build ----------------
__global__ void zero_counts_kernel() {
    int i = blockIdx.x * blockDim.x + threadIdx.x;
    if (i < NN) g_cnt[i] = 0;
}

// count + record within-segment position (so fill needs no atomics)
__global__ void count_kernel(const int* __restrict__ dst) {
    int base = blockIdx.x * 1024 + threadIdx.x;
#pragma unroll
    for (int k = 0; k < 4; k++) {
        int e = base + k * 256;
        int d = dst[e];
        g_epos[e] = atomicAdd(&g_cnt[d], 1);
    }
}

__global__ void scan_kernel() {
    __shared__ int ssum[256];
    int t = threadIdx.x;
    int base = t * 32;
    int vals[32];
    int s = 0;
#pragma unroll
    for (int j = 0; j < 32; j++) { vals[j] = g_cnt[base + j]; s += vals[j]; }
    ssum[t] = s;
    __syncthreads();
#pragma unroll
    for (int off = 1; off < 256; off <<= 1) {
        int v = (t >= off) ? ssum[t - off] : 0;
        __syncthreads();
        ssum[t] += v;
        __syncthreads();
    }
    int run = ssum[t] - s;
#pragma unroll
    for (int j = 0; j < 32; j++) {
        g_rowstart[base + j] = run;
        run += vals[j];
    }
    if (t == 255) g_rowstart[NN] = run;
}

// pure scatter, no atomics
__global__ void fill_kernel(const int* __restrict__ src, const int* __restrict__ dst) {
    int base = blockIdx.x * 1024 + threadIdx.x;
#pragma unroll
    for (int k = 0; k < 4; k++) {
        int e = base + k * 256;
        int d = dst[e];
        g_csr[g_rowstart[d] + g_epos[e]] = src[e];
    }
}

// ---------------- weight fp32 -> bf16 hi/lo split (small, W1/W2/W3 only) ----------------
#define CVT_W1  (HH * FIN / 4)                 // 32768 float4
#define CVT_W2  (LL * HH / 4)                  // 4096
#define CVT_WTOT (CVT_W1 + 2 * CVT_W2)         // 40960

__global__ void conv_w_kernel(const float* __restrict__ W1,
                              const float* __restrict__ W2,
                              const float* __restrict__ W3)
{
    int i = blockIdx.x * blockDim.x + threadIdx.x;
    if (i >= CVT_WTOT) return;
    const float* in;
    __nv_bfloat16 *hi, *lo;
    int j;
    if (i < CVT_W1) {
        j = i;               in = W1;  hi = g_w1hi; lo = g_w1lo;
    } else if (i < CVT_W1 + CVT_W2) {
        j = i - CVT_W1;      in = W2;  hi = g_wchi; lo = g_wclo;
    } else {
        j = i - CVT_W1 - CVT_W2;       in = W3;
        hi = g_wchi + (size_t)LL * HH; lo = g_wclo + (size_t)LL * HH;
    }
    float4 v = ((const float4*)in)[j];
    __nv_bfloat16 h0 = __float2bfloat16(v.x);
    __nv_bfloat16 h1 = __float2bfloat16(v.y);
    __nv_bfloat16 h2 = __float2bfloat16(v.z);
    __nv_bfloat16 h3 = __float2bfloat16(v.w);
    __nv_bfloat16 l0 = __float2bfloat16(v.x - __bfloat162float(h0));
    __nv_bfloat16 l1 = __float2bfloat16(v.y - __bfloat162float(h1));
    __nv_bfloat16 l2 = __float2bfloat16(v.z - __bfloat162float(h2));
    __nv_bfloat16 l3 = __float2bfloat16(v.w - __bfloat162float(h3));
    __nv_bfloat162* hp = (__nv_bfloat162*)(hi + (size_t)j * 4);
    __nv_bfloat162* lp = (__nv_bfloat162*)(lo + (size_t)j * 4);
    hp[0] = __nv_bfloat162(h0, h1);
    hp[1] = __nv_bfloat162(h2, h3);
    lp[0] = __nv_bfloat162(l0, l1);
    lp[1] = __nv_bfloat162(l2, l3);
}

// ---------------- bf16 mma primitive ----------------
__device__ __forceinline__ void mma_bf16(
    float* c, const uint32_t* a, const uint32_t* b)
{
    asm volatile(
        "mma.sync.aligned.m16n8k16.row.col.f32.bf16.bf16.f32 "
        "{%0,%1,%2,%3}, {%4,%5,%6,%7}, {%8,%9}, {%0,%1,%2,%3};"
        : "+f"(c[0]), "+f"(c[1]), "+f"(c[2]), "+f"(c[3])
        : "r"(a[0]), "r"(a[1]), "r"(a[2]), "r"(a[3]), "r"(b[0]), "r"(b[1]));
}

#define LDMATRIX_X4(r0, r1, r2, r3, addr) \
    asm volatile("ldmatrix.sync.aligned.m8n8.x4.shared.b16 {%0,%1,%2,%3}, [%4];" \
        : "=r"(r0), "=r"(r1), "=r"(r2), "=r"(r3) : "r"(addr))

// ---------------- split-bf16 GEMM with inline A split ----------------
// C[M,Nd] = A[M,K](fp32, split inline) @ (Bhi+Blo)[Nd,K]^T, drops lo*lo term.
// CTA 128x64, 8 warps of 32x32, BK=64, smem rows padded to 72 bf16 (144B: bank
// stride 4 words -> ldmatrix conflict-free).
#define G12_SMEM ((128 * 72 + 64 * 72) * 2 * 2)   // 55296 B

__global__ __launch_bounds__(256) void gemm12_kernel(
    const float* __restrict__ A,
    const __nv_bfloat16* __restrict__ Bhi, const __nv_bfloat16* __restrict__ Blo,
    float* __restrict__ C, int Nd, int K)
{
    extern __shared__ __align__(16) char sm12[];
    __nv_bfloat16* sAh = (__nv_bfloat16*)sm12;        // 128*72
    __nv_bfloat16* sAl = sAh + 128 * 72;
    __nv_bfloat16* sBh = sAl + 128 * 72;              // 64*72
    __nv_bfloat16* sBl = sBh + 64 * 72;

    int tid  = threadIdx.x;
    int lane = tid & 31;
    int w    = tid >> 5;
    int wm = (w >> 1) * 32;
    int wn = (w & 1) * 32;
    int grp = lane >> 2;
    int qid = lane & 3;
    int m0 = blockIdx.y * 128;
    int n0 = blockIdx.x * 64;

    // ldmatrix lane addressing (same pattern as gemm3)
    uint32_t sAh32 = (uint32_t)__cvta_generic_to_shared(sAh);
    uint32_t sAl32 = (uint32_t)__cvta_generic_to_shared(sAl);
    uint32_t sBh32 = (uint32_t)__cvta_generic_to_shared(sBh);
    uint32_t sBl32 = (uint32_t)__cvta_generic_to_shared(sBl);
    int a_row = (lane & 7) + ((lane >> 3) & 1) * 8;
    int a_cb  = (lane >> 4) * 16;
    int b_row = (lane & 7) + ((lane >> 4) & 1) * 8;
    int b_cb  = ((lane >> 3) & 1) * 16;
    uint32_t aH[2], aL[2], bH[2], bL[2];
#pragma unroll
    for (int mt = 0; mt < 2; mt++) {
        uint32_t off = (uint32_t)(wm + mt * 16 + a_row) * 144 + a_cb;
        aH[mt] = sAh32 + off;  aL[mt] = sAl32 + off;
    }
#pragma unroll
    for (int np = 0; np < 2; np++) {
        uint32_t off = (uint32_t)(wn + np * 16 + b_row) * 144 + b_cb;
        bH[np] = sBh32 + off;  bL[np] = sBl32 + off;
    }

    float acc[2][4][4];
#pragma unroll
    for (int mt = 0; mt < 2; mt++)
#pragma unroll
        for (int nt = 0; nt < 4; nt++)
#pragma unroll
            for (int r = 0; r < 4; r++) acc[mt][nt][r] = 0.f;

    for (int kt = 0; kt < K; kt += 64) {
        // A: 128 rows x 64 cols fp32, split inline to bf16 hi/lo
#pragma unroll
        for (int it = 0; it < 8; it++) {
            int i = it * 256 + tid;
            int row = i >> 4, u = i & 15;           // 16 float4 per row
            float4 v = *(const float4*)(A + (size_t)(m0 + row) * K + kt + u * 4);
            __nv_bfloat16 h0 = __float2bfloat16(v.x);
            __nv_bfloat16 h1 = __float2bfloat16(v.y);
            __nv_bfloat16 h2 = __float2bfloat16(v.z);
            __nv_bfloat16 h3 = __float2bfloat16(v.w);
            __nv_bfloat16 l0 = __float2bfloat16(v.x - __bfloat162float(h0));
            __nv_bfloat16 l1 = __float2bfloat16(v.y - __bfloat162float(h1));
            __nv_bfloat16 l2 = __float2bfloat16(v.z - __bfloat162float(h2));
            __nv_bfloat16 l3 = __float2bfloat16(v.w - __bfloat162float(h3));
            int so = row * 72 + u * 4;
            __nv_bfloat162 hh0(h0, h1), hh1(h2, h3), ll0(l0, l1), ll1(l2, l3);
            uint2 hv, lv;
            hv.x = *(uint32_t*)&hh0;  hv.y = *(uint32_t*)&hh1;
            lv.x = *(uint32_t*)&ll0;  lv.y = *(uint32_t*)&ll1;
            *(uint2*)(sAh + so) = hv;
            *(uint2*)(sAl + so) = lv;
        }
        // B: presplit bf16
#pragma unroll
        for (int it = 0; it < 2; it++) {
            int i = it * 256 + tid;
            int row = i >> 3, u = i & 7;
            size_t go = (size_t)(n0 + row) * K + kt + u * 8;
            int so = row * 72 + u * 8;
            *(uint4*)(sBh + so) = *(const uint4*)(Bhi + go);
            *(uint4*)(sBl + so) = *(const uint4*)(Blo + go);
        }
        __syncthreads();
#pragma unroll
        for (int ks = 0; ks < 4; ks++) {
            uint32_t koff = ks * 32;                 // 16 bf16 = 32 bytes
            uint32_t ah[2][4], al[2][4], bh[4][2], bl[4][2];
#pragma unroll
            for (int mt = 0; mt < 2; mt++) {
                LDMATRIX_X4(ah[mt][0], ah[mt][1], ah[mt][2], ah[mt][3], aH[mt] + koff);
                LDMATRIX_X4(al[mt][0], al[mt][1], al[mt][2], al[mt][3], aL[mt] + koff);
            }
#pragma unroll
            for (int np = 0; np < 2; np++) {
                LDMATRIX_X4(bh[2*np][0], bh[2*np][1], bh[2*np+1][0], bh[2*np+1][1],
                            bH[np] + koff);
                LDMATRIX_X4(bl[2*np][0], bl[2*np][1], bl[2*np+1][0], bl[2*np+1][1],
                            bL[np] + koff);
            }
#pragma unroll
            for (int mt = 0; mt < 2; mt++)
#pragma unroll
                for (int nt = 0; nt < 4; nt++) {
                    mma_bf16(acc[mt][nt], ah[mt], bh[nt]);
                    mma_bf16(acc[mt][nt], ah[mt], bl[nt]);
                    mma_bf16(acc[mt][nt], al[mt], bh[nt]);
                }
        }
        __syncthreads();
    }

#pragma unroll
    for (int mt = 0; mt < 2; mt++) {
        int row = m0 + wm + mt * 16 + grp;
#pragma unroll
        for (int nt = 0; nt < 4; nt++) {
            int col = n0 + wn + nt * 8 + qid * 2;
            float2 v0 = make_float2(acc[mt][nt][0], acc[mt][nt][1]);
            float2 v1 = make_float2(acc[mt][nt][2], acc[mt][nt][3]);
            *(float2*)(C + (size_t)row * Nd + col)       = v0;
            *(float2*)(C + (size_t)(row + 8) * Nd + col) = v1;
        }
    }
}

// ---------------- aggregation 1: hidden = relu(segsum + b1), fp32 out ----------------
__global__ __launch_bounds__(256) void agg1_relu_kernel(const float* __restrict__ b1) {
    int node = blockIdx.x * 4 + (threadIdx.x >> 6);
    int lane = threadIdx.x & 63;
    int s = g_rowstart[node];
    int e = g_rowstart[node + 1];
    float4 acc = make_float4(0.f, 0.f, 0.f, 0.f);
    int j = s;
    for (; j + 4 <= e; j += 4) {
        int i0 = g_csr[j + 0], i1 = g_csr[j + 1], i2 = g_csr[j + 2], i3 = g_csr[j + 3];
        float4 v0 = *(const float4*)(g_X1 + (size_t)i0 * HH + lane * 4);
        float4 v1 = *(const float4*)(g_X1 + (size_t)i1 * HH + lane * 4);
        float4 v2 = *(const float4*)(g_X1 + (size_t)i2 * HH + lane * 4);
        float4 v3 = *(const float4*)(g_X1 + (size_t)i3 * HH + lane * 4);
        acc.x += v0.x + v1.x + v2.x + v3.x;
        acc.y += v0.y + v1.y + v2.y + v3.y;
        acc.z += v0.z + v1.z + v2.z + v3.z;
        acc.w += v0.w + v1.w + v2.w + v3.w;
    }
    for (; j < e; j++) {
        int i0 = g_csr[j];
        float4 v0 = *(const float4*)(g_X1 + (size_t)i0 * HH + lane * 4);
        acc.x += v0.x; acc.y += v0.y; acc.z += v0.z; acc.w += v0.w;
    }
    float4 bb = ((const float4*)b1)[lane];
    float4 r;
    r.x = fmaxf(acc.x + bb.x, 0.f);
    r.y = fmaxf(acc.y + bb.y, 0.f);
    r.z = fmaxf(acc.z + bb.z, 0.f);
    r.w = fmaxf(acc.w + bb.w, 0.f);
    *(float4*)(g_hidden + (size_t)node * HH + lane * 4) = r;
}

// ---------------- aggregation 2: mu/logvar + fused z split into Acat/Bcat ----------------
__global__ __launch_bounds__(256) void agg2_bias_kernel(
    const float* __restrict__ b2, const float* __restrict__ b3,
    float* __restrict__ out_mu, float* __restrict__ out_lv)
{
    int node = blockIdx.x * 8 + (threadIdx.x >> 5);
    int lane = threadIdx.x & 31;
    int s = g_rowstart[node];
    int e = g_rowstart[node + 1];
    float4 acc = make_float4(0.f, 0.f, 0.f, 0.f);
    int j = s;
    for (; j + 4 <= e; j += 4) {
        int i0 = g_csr[j + 0], i1 = g_csr[j + 1], i2 = g_csr[j + 2], i3 = g_csr[j + 3];
        float4 v0 = *(const float4*)(g_P + (size_t)i0 * P2 + lane * 4);
        float4 v1 = *(const float4*)(g_P + (size_t)i1 * P2 + lane * 4);
        float4 v2 = *(const float4*)(g_P + (size_t)i2 * P2 + lane * 4);
        float4 v3 = *(const float4*)(g_P + (size_t)i3 * P2 + lane * 4);
        acc.x += v0.x + v1.x + v2.x + v3.x;
        acc.y += v0.y + v1.y + v2.y + v3.y;
        acc.z += v0.z + v1.z + v2.z + v3.z;
        acc.w += v0.w + v1.w + v2.w + v3.w;
    }
    for (; j < e; j++) {
        int i0 = g_csr[j];
        float4 v0 = *(const float4*)(g_P + (size_t)i0 * P2 + lane * 4);
        acc.x += v0.x; acc.y += v0.y; acc.z += v0.z; acc.w += v0.w;
    }
    if (lane < 16) {
        float4 bb = ((const float4*)b2)[lane];
        acc.x += bb.x; acc.y += bb.y; acc.z += bb.z; acc.w += bb.w;
        *(float4*)(out_mu + (size_t)node * LL + lane * 4) = acc;
        float zv[4] = {acc.x, acc.y, acc.z, acc.w};
        __nv_bfloat16* a = g_Acat + (size_t)node * 192 + lane * 4;
        __nv_bfloat16* b = g_Bcat + (size_t)node * 192 + lane * 4;
#pragma unroll
        for (int k = 0; k < 4; k++) {
            __nv_bfloat16 h = __float2bfloat16(zv[k]);
            __nv_bfloat16 l = __float2bfloat16(zv[k] - __bfloat162float(h));
            a[k] = h;  a[64 + k] = h;  a[128 + k] = l;
            b[k] = h;  b[64 + k] = l;  b[128 + k] = h;
        }
    } else {
        float4 bb = ((const float4*)b3)[lane - 16];
        acc.x += bb.x; acc.y += bb.y; acc.z += bb.z; acc.w += bb.w;
        *(float4*)(out_lv + (size_t)node * LL + (lane - 16) * 4) = acc;
    }
}

// ---------------- adj = sigmoid(Z @ Z^T) via mma.sync bf16 (split, K=192) ----------------
__device__ __forceinline__ float sigmoid_tanh(float x) {
    float t;
    asm("tanh.approx.f32 %0, %1;" : "=f"(t) : "f"(0.5f * x));
    return 0.5f * t + 0.5f;
}

// CTA 128x128, 4 warps of 64x64 each, K=192 resident. Rows padded to 200 bf16.
// Triangular 1-D grid (2080 CTAs); off-diagonal blocks mirror-write transposed.
#define G3_PAD   200
#define G3_ASZ   (128 * G3_PAD * 2)
#define G3_SMEM  (2 * G3_ASZ)

__global__ __launch_bounds__(128, 2) void gemm3_mma_kernel(float* __restrict__ adj)
{
    int t = blockIdx.x;
    int by = (int)((sqrtf(8.f * (float)t + 1.f) - 1.f) * 0.5f);
    while ((by + 1) * (by + 2) / 2 <= t) by++;
    while (by * (by + 1) / 2 > t) by--;
    int bx = t - by * (by + 1) / 2;

    extern __shared__ __align__(16) char smem[];
    __nv_bfloat16* sA = (__nv_bfloat16*)smem;
    __nv_bfloat16* sB = (__nv_bfloat16*)(smem + G3_ASZ);

    int tid  = threadIdx.x;
    int lane = tid & 31;
    int w    = tid >> 5;
    int m0 = by * 128;
    int n0 = bx * 128;
    bool diag = (bx == by);

    for (int i = tid; i < 2 * 128 * 24; i += 128) {
        int tt  = (i >= 3072);
        int j   = tt ? i - 3072 : i;
        int row = j / 24;
        int u   = j % 24;
        const __nv_bfloat16* g =
            (tt ? g_Bcat + (size_t)(n0 + row) * 192
                : g_Acat + (size_t)(m0 + row) * 192) + u * 8;
        __nv_bfloat16* d = (tt ? sB : sA) + row * G3_PAD + u * 8;
        *(uint4*)d = *(const uint4*)g;
    }
    __syncthreads();

    int wm = (w >> 1) * 64;
    int wn = (w & 1) * 64;
    int grp = lane >> 2;
    int qid = lane & 3;

    uint32_t sA32 = (uint32_t)__cvta_generic_to_shared(sA);
    uint32_t sB32 = (uint32_t)__cvta_generic_to_shared(sB);
    int a_row = (lane & 7) + ((lane >> 3) & 1) * 8;
    int a_cb  = (lane >> 4) * 16;
    int b_row = (lane & 7) + ((lane >> 4) & 1) * 8;
    int b_cb  = ((lane >> 3) & 1) * 16;
    uint32_t a_addr[4], b_addr[4];
#pragma unroll
    for (int mt = 0; mt < 4; mt++)
        a_addr[mt] = sA32 + (uint32_t)(wm + mt * 16 + a_row) * (G3_PAD * 2) + a_cb;
#pragma unroll
    for (int np = 0; np < 4; np++)
        b_addr[np] = sB32 + (uint32_t)(wn + np * 16 + b_row) * (G3_PAD * 2) + b_cb;

    float acc[4][8][4];
#pragma unroll
    for (int mt = 0; mt < 4; mt++)
#pragma unroll
        for (int nt = 0; nt < 8; nt++)
#pragma unroll
            for (int r = 0; r < 4; r++) acc[mt][nt][r] = 0.f;

#pragma unroll
    for (int ks = 0; ks < 12; ks++) {
        uint32_t koff = ks * 32;
        uint32_t a[4][4], b[8][2];
#pragma unroll
        for (int mt = 0; mt < 4; mt++)
            LDMATRIX_X4(a[mt][0], a[mt][1], a[mt][2], a[mt][3], a_addr[mt] + koff);
#pragma unroll
        for (int np = 0; np < 4; np++)
            LDMATRIX_X4(b[2 * np][0], b[2 * np][1], b[2 * np + 1][0], b[2 * np + 1][1],
                        b_addr[np] + koff);
#pragma unroll
        for (int mt = 0; mt < 4; mt++)
#pragma unroll
            for (int nt = 0; nt < 8; nt++)
                mma_bf16(acc[mt][nt], a[mt], b[nt]);
    }

#pragma unroll
    for (int mt = 0; mt < 4; mt++) {
        int row = m0 + wm + mt * 16 + grp;
#pragma unroll
        for (int nt = 0; nt < 8; nt++) {
            int col = n0 + wn + nt * 8 + qid * 2;
            float s0 = sigmoid_tanh(acc[mt][nt][0]);
            float s1 = sigmoid_tanh(acc[mt][nt][1]);
            float s2 = sigmoid_tanh(acc[mt][nt][2]);
            float s3 = sigmoid_tanh(acc[mt][nt][3]);
            *(float2*)(adj + (size_t)row * NN + col)       = make_float2(s0, s1);
            *(float2*)(adj + (size_t)(row + 8) * NN + col) = make_float2(s2, s3);
            if (!diag) {
                adj[(size_t)col * NN + row]           = s0;
                adj[(size_t)(col + 1) * NN + row]     = s1;
                adj[(size_t)col * NN + row + 8]       = s2;
                adj[(size_t)(col + 1) * NN + row + 8] = s3;
            }
        }
    }
}

// ---------------- launch ----------------
extern "C" void kernel_launch(void* const* d_in, const int* in_sizes, int n_in,
                              void* d_out, int out_size)
{
    const float* features = (const float*)d_in[0];
    const int*   src      = (const int*)  d_in[1];
    const int*   dst      = (const int*)  d_in[2];
    const float* W1       = (const float*)d_in[3];
    const float* b1       = (const float*)d_in[4];
    const float* W2       = (const float*)d_in[5];
    const float* b2       = (const float*)d_in[6];
    const float* W3       = (const float*)d_in[7];
    const float* b3       = (const float*)d_in[8];

    float* adj = (float*)d_out;
    float* mu  = adj + (size_t)NN * NN;
    float* lv  = mu  + (size_t)NN * LL;

    float *x1p, *hidp, *pp;
    cudaGetSymbolAddress((void**)&x1p,  g_X1);
    cudaGetSymbolAddress((void**)&hidp, g_hidden);
    cudaGetSymbolAddress((void**)&pp,   g_P);

    __nv_bfloat16 *w1hi, *w1lo, *wchi, *wclo;
    cudaGetSymbolAddress((void**)&w1hi, g_w1hi);
    cudaGetSymbolAddress((void**)&w1lo, g_w1lo);
    cudaGetSymbolAddress((void**)&wchi, g_wchi);
    cudaGetSymbolAddress((void**)&wclo, g_wclo);

    cudaFuncSetAttribute(gemm3_mma_kernel,
                         cudaFuncAttributeMaxDynamicSharedMemorySize, G3_SMEM);
    cudaFuncSetAttribute(gemm12_kernel,
                         cudaFuncAttributeMaxDynamicSharedMemorySize, G12_SMEM);

    // side stream + fork/join events (infra, created once; no device memory)
    static cudaStream_t s2 = nullptr;
    static cudaEvent_t ev_fork = nullptr, ev_join = nullptr;
    if (s2 == nullptr) {
        cudaStreamCreateWithFlags(&s2, cudaStreamNonBlocking);
        cudaEventCreateWithFlags(&ev_fork, cudaEventDisableTiming);
        cudaEventCreateWithFlags(&ev_join, cudaEventDisableTiming);
    }

    // ---- fork: CSR chain on side stream, conv+gemm1 on main stream ----
    cudaEventRecord(ev_fork, 0);
    cudaStreamWaitEvent(s2, ev_fork, 0);

    zero_counts_kernel<<<NN / 256, 256, 0, s2>>>();
    count_kernel<<<EE / 1024, 256, 0, s2>>>(dst);
    scan_kernel<<<1, 256, 0, s2>>>();
    fill_kernel<<<EE / 1024, 256, 0, s2>>>(src, dst);
    cudaEventRecord(ev_join, s2);

    // main stream: tiny weight splits, then gemm1 (features split inline)
    conv_w_kernel<<<(CVT_WTOT + 255) / 256, 256>>>(W1, W2, W3);
    gemm12_kernel<<<dim3(HH / 64, NN / 128), 256, G12_SMEM>>>(
        features, w1hi, w1lo, x1p, HH, FIN);

    // ---- join ----
    cudaStreamWaitEvent(0, ev_join, 0);

    // hidden = relu(segsum(X1) + b1)  (fp32)
    agg1_relu_kernel<<<NN / 4, 256>>>(b1);

    // P = hidden @ [W2;W3]^T   [8192,128]  (hidden split inline)
    gemm12_kernel<<<dim3(P2 / 64, NN / 128), 256, G12_SMEM>>>(
        hidp, wchi, wclo, pp, P2, HH);

    // mu / logvar = segsum(P) + b2/b3, with fused z-split into Acat/Bcat
    agg2_bias_kernel<<<NN / 8, 256>>>(b2, b3, mu, lv);

    // adj = sigmoid(Z @ Z^T) via mma.sync split-bf16, K=192, symmetric
    gemm3_mma_kernel<<<2080, 128, G3_SMEM>>>(adj);
}